// round 6
// baseline (speedup 1.0000x reference)
#include <cuda_runtime.h>
#include <cuda_fp16.h>

#define NN 100000
#define EE 3200000
#define IN_DIM 256
#define H1 32
#define H2 64
#define WPAD 260
#define G1_SMEM ((32 * WPAD + 64 * 256) * 4)

// ---------------- static device scratch -------------------------------------
__device__ __align__(256) float   g_h1[NN * H1];   // x@W1 (fp32, unscaled)
__device__ __align__(256) __half2 g_h1h[NN * 16];  // scaled h1, pairs (c, c+16)
__device__ __align__(256) __half2 g_h2h[NN * 32];  // (z1@W2)*dinv, pairs (c, c+32)
__device__ int   g_cnt[NN];
__device__ int   g_rowptr[NN + 1];
__device__ int   g_pos[NN];
__device__ int   g_col[EE];
__device__ float g_dinv[NN];
__device__ int   g_bsum[256];
__device__ float g_part[2048];
__device__ float g_scalar[2];
__device__ int   g_flag;        // 1 if edge index int64, 0 if int32

// ------------- launch 0: zero counters + detect edge dtype ------------------
__global__ void detect_zero_kernel(const unsigned int* __restrict__ w, int n_vals, int N) {
    int i = blockIdx.x * blockDim.x + threadIdx.x;
    if (i < N) g_cnt[i] = 0;
    if (blockIdx.x == 0) {
        __shared__ unsigned int acc;
        if (threadIdx.x == 0) acc = 0u;
        __syncthreads();
        int K = n_vals < 2048 ? n_vals : 2048;
        unsigned int v = 0u;
        for (int j = threadIdx.x; j < K; j += blockDim.x) v |= w[2 * j + 1];
        atomicOr(&acc, v);
        __syncthreads();
        if (threadIdx.x == 0) g_flag = (acc == 0u) ? 1 : 0;
    }
}

// ------------- launch 1: histogram of dst (2 edges/thread) ------------------
__global__ void hist_kernel(const int* __restrict__ buf, int E) {
    int e = (blockIdx.x * blockDim.x + threadIdx.x) * 2;
    if (e + 1 < E) {
        int d0, d1;
        if (g_flag) { int4 v = *(const int4*)&buf[2 * (E + e)]; d0 = v.x; d1 = v.z; }
        else        { int2 v = *(const int2*)&buf[E + e];       d0 = v.x; d1 = v.y; }
        atomicAdd(&g_cnt[d0], 1);
        atomicAdd(&g_cnt[d1], 1);
    } else if (e < E) {
        int d = g_flag ? buf[2 * (E + e)] : buf[E + e];
        atomicAdd(&g_cnt[d], 1);
    }
}

__global__ void hist_kernel_s(const int* __restrict__ buf, int E) {
    int e = blockIdx.x * blockDim.x + threadIdx.x;
    if (e < E) {
        int d = g_flag ? buf[2 * (E + e)] : buf[E + e];
        atomicAdd(&g_cnt[d], 1);
    }
}

// ------------- launch 2: block scan -----------------------------------------
__global__ void scan1_kernel(int N) {
    __shared__ int sm[1024];
    int t = threadIdx.x;
    int i = blockIdx.x * 1024 + t;
    int x = (i < N) ? g_cnt[i] : 0;
    sm[t] = x;
    __syncthreads();
    for (int off = 1; off < 1024; off <<= 1) {
        int v = (t >= off) ? sm[t - off] : 0;
        __syncthreads();
        sm[t] += v;
        __syncthreads();
    }
    if (i < N) g_rowptr[i] = sm[t] - x;
    if (t == 1023) g_bsum[blockIdx.x] = sm[1023];
}

// ------------- launch 3 (PROFILED): GEMM1 via smem-staged x -----------------
// Block stages a 64-row x tile coalesced; warps compute 8 rows each from
// broadcast LDS. W transposed+padded for conflict-free LDS.128.
__global__ void gemm1_kernel(const float* __restrict__ x,
                             const float* __restrict__ W1, int N) {
    extern __shared__ float sm[];
    float* Wt = sm;                    // 32 * 260
    float* xs = sm + 32 * WPAD;        // 64 * 256
    int t = threadIdx.x;
    for (int i = t; i < IN_DIM * H1; i += 256) {
        int k = i >> 5, c = i & 31;
        Wt[c * WPAD + k] = W1[i];
    }
    int tile0 = blockIdx.x * 64;
    const float4* x4 = (const float4*)x;
    float4* xs4 = (float4*)xs;
    long base = (long)tile0 * 64;
    long lim  = (long)N * 64;
    for (int i = t; i < 4096; i += 256) {
        long gi = base + i;
        xs4[i] = (gi < lim) ? x4[gi] : make_float4(0.f, 0.f, 0.f, 0.f);
    }
    __syncthreads();
    int lane = t & 31, wid = t >> 5;
    int r0 = tile0 + wid * 8;
    const float4* wrow = (const float4*)&Wt[lane * WPAD];
    const float4* xr = xs4 + (wid * 8) * 64;
    float acc0 = 0.f, acc1 = 0.f, acc2 = 0.f, acc3 = 0.f;
    float acc4 = 0.f, acc5 = 0.f, acc6 = 0.f, acc7 = 0.f;
    #pragma unroll 4
    for (int k4 = 0; k4 < 64; k4++) {
        float4 w = wrow[k4];
        float4 v0 = xr[0 * 64 + k4];
        float4 v1 = xr[1 * 64 + k4];
        float4 v2 = xr[2 * 64 + k4];
        float4 v3 = xr[3 * 64 + k4];
        float4 v4 = xr[4 * 64 + k4];
        float4 v5 = xr[5 * 64 + k4];
        float4 v6 = xr[6 * 64 + k4];
        float4 v7 = xr[7 * 64 + k4];
        acc0 = fmaf(v0.x, w.x, acc0); acc0 = fmaf(v0.y, w.y, acc0);
        acc0 = fmaf(v0.z, w.z, acc0); acc0 = fmaf(v0.w, w.w, acc0);
        acc1 = fmaf(v1.x, w.x, acc1); acc1 = fmaf(v1.y, w.y, acc1);
        acc1 = fmaf(v1.z, w.z, acc1); acc1 = fmaf(v1.w, w.w, acc1);
        acc2 = fmaf(v2.x, w.x, acc2); acc2 = fmaf(v2.y, w.y, acc2);
        acc2 = fmaf(v2.z, w.z, acc2); acc2 = fmaf(v2.w, w.w, acc2);
        acc3 = fmaf(v3.x, w.x, acc3); acc3 = fmaf(v3.y, w.y, acc3);
        acc3 = fmaf(v3.z, w.z, acc3); acc3 = fmaf(v3.w, w.w, acc3);
        acc4 = fmaf(v4.x, w.x, acc4); acc4 = fmaf(v4.y, w.y, acc4);
        acc4 = fmaf(v4.z, w.z, acc4); acc4 = fmaf(v4.w, w.w, acc4);
        acc5 = fmaf(v5.x, w.x, acc5); acc5 = fmaf(v5.y, w.y, acc5);
        acc5 = fmaf(v5.z, w.z, acc5); acc5 = fmaf(v5.w, w.w, acc5);
        acc6 = fmaf(v6.x, w.x, acc6); acc6 = fmaf(v6.y, w.y, acc6);
        acc6 = fmaf(v6.z, w.z, acc6); acc6 = fmaf(v6.w, w.w, acc6);
        acc7 = fmaf(v7.x, w.x, acc7); acc7 = fmaf(v7.y, w.y, acc7);
        acc7 = fmaf(v7.z, w.z, acc7); acc7 = fmaf(v7.w, w.w, acc7);
    }
    if (r0 + 0 < N) g_h1[(r0 + 0) * H1 + lane] = acc0;
    if (r0 + 1 < N) g_h1[(r0 + 1) * H1 + lane] = acc1;
    if (r0 + 2 < N) g_h1[(r0 + 2) * H1 + lane] = acc2;
    if (r0 + 3 < N) g_h1[(r0 + 3) * H1 + lane] = acc3;
    if (r0 + 4 < N) g_h1[(r0 + 4) * H1 + lane] = acc4;
    if (r0 + 5 < N) g_h1[(r0 + 5) * H1 + lane] = acc5;
    if (r0 + 6 < N) g_h1[(r0 + 6) * H1 + lane] = acc6;
    if (r0 + 7 < N) g_h1[(r0 + 7) * H1 + lane] = acc7;
}

// ------------- launch 4/5: scan finish + dinv + scale + fp16-pack h1 --------
__global__ void scan2_kernel(int nb) {
    if (threadIdx.x == 0 && blockIdx.x == 0) {
        int run = 0;
        for (int b = 0; b < nb; b++) { int v = g_bsum[b]; g_bsum[b] = run; run += v; }
    }
}

__global__ void scan3_kernel(int N, int E) {
    int i = blockIdx.x * blockDim.x + threadIdx.x;
    if (i < N) {
        int r = g_rowptr[i] + g_bsum[i >> 10];
        g_rowptr[i] = r;
        g_pos[i]    = r;
        float di = rsqrtf((float)(g_cnt[i] + 1));
        g_dinv[i] = di;
        float ch[32];
        const float4* h = (const float4*)&g_h1[i * H1];
        #pragma unroll
        for (int j = 0; j < 8; j++) {
            float4 v = h[j];
            ch[4 * j + 0] = v.x * di; ch[4 * j + 1] = v.y * di;
            ch[4 * j + 2] = v.z * di; ch[4 * j + 3] = v.w * di;
        }
        #pragma unroll
        for (int p = 0; p < 16; p++)
            g_h1h[i * 16 + p] = __floats2half2_rn(ch[p], ch[p + 16]);
        if (i == 0) g_rowptr[N] = E;
    }
}

// ------------- launch 6: CSR fill (2 edges/thread) --------------------------
__global__ void fill_kernel(const int* __restrict__ buf, int E) {
    int e = (blockIdx.x * blockDim.x + threadIdx.x) * 2;
    if (e + 1 < E) {
        int s0, s1, d0, d1;
        if (g_flag) {
            int4 sv = *(const int4*)&buf[2 * e];        s0 = sv.x; s1 = sv.z;
            int4 dv = *(const int4*)&buf[2 * (E + e)];  d0 = dv.x; d1 = dv.z;
        } else {
            int2 sv = *(const int2*)&buf[e];        s0 = sv.x; s1 = sv.y;
            int2 dv = *(const int2*)&buf[E + e];    d0 = dv.x; d1 = dv.y;
        }
        int p0 = atomicAdd(&g_pos[d0], 1); g_col[p0] = s0;
        int p1 = atomicAdd(&g_pos[d1], 1); g_col[p1] = s1;
    } else if (e < E) {
        int s, d;
        if (g_flag) { d = buf[2 * (E + e)]; s = buf[2 * e]; }
        else        { d = buf[E + e];       s = buf[e]; }
        int p = atomicAdd(&g_pos[d], 1);
        g_col[p] = s;
    }
}

__global__ void fill_kernel_s(const int* __restrict__ buf, int E) {
    int e = blockIdx.x * blockDim.x + threadIdx.x;
    if (e < E) {
        int s, d;
        if (g_flag) { d = buf[2 * (E + e)]; s = buf[2 * e]; }
        else        { d = buf[E + e];       s = buf[e]; }
        int p = atomicAdd(&g_pos[d], 1);
        g_col[p] = s;
    }
}

// ------------- launch 7: agg1 (fp16, 2 edges/warp-iter) + GEMM2 fused -------
__global__ void agg1_gemm2_kernel(const float* __restrict__ b1,
                                  const float* __restrict__ W2, int N) {
    __shared__ float2 Wp[H1 * 32];   // Wp[k*32+c] = (W2[k][c], W2[k][c+32])
    int t = threadIdx.x;
    for (int i = t; i < H1 * 32; i += blockDim.x) {
        int k = i >> 5, c2 = i & 31;
        Wp[i] = make_float2(W2[k * H2 + c2], W2[k * H2 + 32 + c2]);
    }
    __syncthreads();
    int lane = t & 31;
    int c = lane & 15;
    int hb = (lane >> 4) << 4;   // 0 or 16
    int gw = (blockIdx.x * blockDim.x + t) >> 5;
    int nw = (gridDim.x * blockDim.x) >> 5;
    float bias0 = b1[c], bias1 = b1[c + 16];
    for (int d = gw; d < N; d += nw) {
        int beg = g_rowptr[d], end = g_rowptr[d + 1];
        float aAx = 0.f, aAy = 0.f, aBx = 0.f, aBy = 0.f;
        int e = beg;
        for (; e + 32 <= end; e += 32) {
            int cv = g_col[e + lane];
            #pragma unroll
            for (int j = 0; j < 16; j += 2) {
                int s0 = __shfl_sync(0xffffffffu, cv, j + hb);
                int s1 = __shfl_sync(0xffffffffu, cv, j + 1 + hb);
                float2 f0 = __half22float2(g_h1h[s0 * 16 + c]);
                float2 f1 = __half22float2(g_h1h[s1 * 16 + c]);
                aAx += f0.x; aAy += f0.y;
                aBx += f1.x; aBy += f1.y;
            }
        }
        if (e < end) {
            int n = end - e;
            int cv = (e + lane < end) ? g_col[e + lane] : 0;
            int hodd = hb >> 4;                  // 0 or 1
            for (int j = 0; j < n; j += 2) {
                int idx = j + hodd;
                int s = __shfl_sync(0xffffffffu, cv, idx < n ? idx : 0);
                if (idx < n) {
                    float2 f = __half22float2(g_h1h[s * 16 + c]);
                    aAx += f.x; aAy += f.y;
                }
            }
        }
        float ax = aAx + aBx, ay = aAy + aBy;
        ax += __shfl_xor_sync(0xffffffffu, ax, 16);
        ay += __shfl_xor_sync(0xffffffffu, ay, 16);
        float2 sf = __half22float2(g_h1h[d * 16 + c]);   // self loop
        float di = g_dinv[d];
        float z0  = fmaxf(di * (ax + sf.x) + bias0, 0.f);   // z[c]
        float z16 = fmaxf(di * (ay + sf.y) + bias1, 0.f);   // z[c+16]
        // GEMV: h2 = (z1 @ W2) * dinv
        float a0 = 0.f, a1 = 0.f;
        #pragma unroll
        for (int k = 0; k < 16; k++) {
            float zka = __shfl_sync(0xffffffffu, z0, k);    // z[k]
            float zkb = __shfl_sync(0xffffffffu, z16, k);   // z[k+16]
            float2 wa = Wp[k * 32 + lane];
            float2 wb = Wp[(k + 16) * 32 + lane];
            a0 = fmaf(zka, wa.x, a0); a1 = fmaf(zka, wa.y, a1);
            a0 = fmaf(zkb, wb.x, a0); a1 = fmaf(zkb, wb.y, a1);
        }
        g_h2h[d * 32 + lane] = __floats2half2_rn(a0 * di, a1 * di);
    }
}

// ------------- launch 8: agg2 (fp16 gather) + MLP head + exp + block sums ---
__global__ void agg2_mlp_kernel(const float* __restrict__ b2,
                                const float* __restrict__ Wo1, const float* __restrict__ bo1,
                                const float* __restrict__ Wo2, const float* __restrict__ bo2,
                                float* __restrict__ out, int N) {
    __shared__ float2 W1p[64 * 32];  // (Wo1[j][c], Wo1[j][c+32])
    __shared__ float2 W2p[64 * 32];
    __shared__ float b1s[64], b2s[64], bb[64];
    __shared__ float wsum[8];
    int t = threadIdx.x;
    for (int i = t; i < 64 * 32; i += blockDim.x) {
        int j = i >> 5, c = i & 31;
        W1p[i] = make_float2(Wo1[j * 64 + c], Wo1[j * 64 + 32 + c]);
        W2p[i] = make_float2(Wo2[j * 64 + c], Wo2[j * 64 + 32 + c]);
    }
    if (t < 64) { b1s[t] = bo1[t]; b2s[t] = bo2[t]; bb[t] = b2[t]; }
    __syncthreads();
    int lane = t & 31, wid = t >> 5;
    int gw = blockIdx.x * 8 + wid, nw = gridDim.x * 8;
    float bias0 = bb[lane], bias1 = bb[lane + 32];
    float ssum = 0.f;
    for (int d = gw; d < N; d += nw) {
        int beg = g_rowptr[d], end = g_rowptr[d + 1];
        float2 self = __half22float2(g_h2h[d * 32 + lane]);
        float a00 = self.x, a10 = self.y;
        float a01 = 0.f, a11 = 0.f;
        int e = beg;
        for (; e + 32 <= end; e += 32) {
            int cv = g_col[e + lane];
            #pragma unroll
            for (int j = 0; j < 32; j += 2) {
                int s0 = __shfl_sync(0xffffffffu, cv, j);
                int s1 = __shfl_sync(0xffffffffu, cv, j + 1);
                float2 f0 = __half22float2(g_h2h[s0 * 32 + lane]);
                float2 f1 = __half22float2(g_h2h[s1 * 32 + lane]);
                a00 += f0.x; a10 += f0.y;
                a01 += f1.x; a11 += f1.y;
            }
        }
        if (e < end) {
            int n = end - e;
            int cv = (e + lane < end) ? g_col[e + lane] : 0;
            for (int j = 0; j < n; j++) {
                int s = __shfl_sync(0xffffffffu, cv, j);
                float2 f = __half22float2(g_h2h[s * 32 + lane]);
                a00 += f.x; a10 += f.y;
            }
        }
        float a0 = a00 + a01, a1 = a10 + a11;
        float di = g_dinv[d];
        float t0 = fmaxf(di * a0 + bias0, 0.f);
        float t1 = fmaxf(di * a1 + bias1, 0.f);
        // layer 1
        float u0 = b1s[lane], u1 = b1s[lane + 32];
        #pragma unroll
        for (int j = 0; j < 32; j++) {
            float tk = __shfl_sync(0xffffffffu, t0, j);
            float2 w = W1p[j * 32 + lane];
            u0 = fmaf(tk, w.x, u0);
            u1 = fmaf(tk, w.y, u1);
        }
        #pragma unroll
        for (int j = 0; j < 32; j++) {
            float tk = __shfl_sync(0xffffffffu, t1, j);
            float2 w = W1p[(j + 32) * 32 + lane];
            u0 = fmaf(tk, w.x, u0);
            u1 = fmaf(tk, w.y, u1);
        }
        u0 = fmaxf(u0, 0.f); u1 = fmaxf(u1, 0.f);
        // layer 2
        float l0 = b2s[lane], l1 = b2s[lane + 32];
        #pragma unroll
        for (int j = 0; j < 32; j++) {
            float uk = __shfl_sync(0xffffffffu, u0, j);
            float2 w = W2p[j * 32 + lane];
            l0 = fmaf(uk, w.x, l0);
            l1 = fmaf(uk, w.y, l1);
        }
        #pragma unroll
        for (int j = 0; j < 32; j++) {
            float uk = __shfl_sync(0xffffffffu, u1, j);
            float2 w = W2p[(j + 32) * 32 + lane];
            l0 = fmaf(uk, w.x, l0);
            l1 = fmaf(uk, w.y, l1);
        }
        float e0 = __expf(l0), e1 = __expf(l1);
        out[d * 64 + lane]      = e0;
        out[d * 64 + 32 + lane] = e1;
        ssum += e0 + e1;
    }
    #pragma unroll
    for (int o = 16; o > 0; o >>= 1) ssum += __shfl_xor_sync(0xffffffffu, ssum, o);
    if (lane == 0) wsum[wid] = ssum;
    __syncthreads();
    if (t == 0) {
        float s = 0.f;
        #pragma unroll
        for (int i = 0; i < 8; i++) s += wsum[i];
        g_part[blockIdx.x] = s;
    }
}

// ------------- launches 9/10: finish softmax --------------------------------
__global__ void reduce_sum_kernel(int n) {
    __shared__ float ws[8];
    int t = threadIdx.x, lane = t & 31, wid = t >> 5;
    float s = 0.f;
    for (int i = t; i < n; i += blockDim.x) s += g_part[i];
    #pragma unroll
    for (int o = 16; o > 0; o >>= 1) s += __shfl_xor_sync(0xffffffffu, s, o);
    if (lane == 0) ws[wid] = s;
    __syncthreads();
    if (t == 0) {
        float r = 0.f;
        for (int i = 0; i < (int)(blockDim.x >> 5); i++) r += ws[i];
        g_scalar[1] = 1.0f / r;
    }
}

__global__ void normalize_kernel(float* __restrict__ out, int total) {
    float inv = g_scalar[1];
    int i = (blockIdx.x * blockDim.x + threadIdx.x) * 4;
    if (i + 3 < total) {
        float4 v = *(float4*)(out + i);
        v.x *= inv; v.y *= inv; v.z *= inv; v.w *= inv;
        *(float4*)(out + i) = v;
    } else {
        for (int j = i; j < total; j++) out[j] *= inv;
    }
}

// ---------------- launch ----------------------------------------------------
extern "C" void kernel_launch(void* const* d_in, const int* in_sizes, int n_in,
                              void* d_out, int out_size) {
    const float* x  = (const float*)d_in[0];
    const int*   ei = (const int*)d_in[1];
    int base = n_in - 8;   // last 8: W1,b1,W2,b2,Wo1,bo1,Wo2,bo2
    const float* W1  = (const float*)d_in[base + 0];
    const float* b1  = (const float*)d_in[base + 1];
    const float* W2  = (const float*)d_in[base + 2];
    const float* b2  = (const float*)d_in[base + 3];
    const float* Wo1 = (const float*)d_in[base + 4];
    const float* bo1 = (const float*)d_in[base + 5];
    const float* Wo2 = (const float*)d_in[base + 6];
    const float* bo2 = (const float*)d_in[base + 7];
    float* out = (float*)d_out;

    int N = in_sizes[0] / IN_DIM;
    int E = in_sizes[1] / 2;
    int nb_scan = (N + 1023) / 1024;
    bool evenE = (E % 2) == 0;

    static bool attr_set = false;
    if (!attr_set) {
        cudaFuncSetAttribute(gemm1_kernel,
                             cudaFuncAttributeMaxDynamicSharedMemorySize, G1_SMEM);
        attr_set = true;
    }

    // 0: zero cnt + dtype detect
    detect_zero_kernel<<<(N + 255) / 256, 256>>>((const unsigned int*)ei, 2 * E, N);
    // 1: histogram
    if (evenE) hist_kernel<<<(E / 2 + 255) / 256, 256>>>(ei, E);
    else       hist_kernel_s<<<(E + 255) / 256, 256>>>(ei, E);
    // 2: scan
    scan1_kernel<<<nb_scan, 1024>>>(N);
    // 3: GEMM1 (profiled slot)
    gemm1_kernel<<<(N + 63) / 64, 256, G1_SMEM>>>(x, W1, N);
    // 4/5: scan finish + dinv + scale + fp16-pack h1
    scan2_kernel<<<1, 32>>>(nb_scan);
    scan3_kernel<<<(N + 255) / 256, 256>>>(N, E);
    // 6: CSR fill
    if (evenE) fill_kernel<<<(E / 2 + 255) / 256, 256>>>(ei, E);
    else       fill_kernel_s<<<(E + 255) / 256, 256>>>(ei, E);
    // 7: agg1 (fp16) + gemm2
    agg1_gemm2_kernel<<<2048, 256>>>(b1, W2, N);
    // 8: agg2 + MLP + exp + block sums
    agg2_mlp_kernel<<<1024, 256>>>(b2, Wo1, bo1, Wo2, bo2, out, N);
    // 9/10: softmax finish
    int total = out_size;
    reduce_sum_kernel<<<1, 256>>>(1024);
    normalize_kernel<<<(total / 4 + 255) / 256, 256>>>(out, total);
}

// round 7
// speedup vs baseline: 1.0559x; 1.0559x over previous
#include <cuda_runtime.h>
#include <cuda_fp16.h>

#define NN 100000
#define EE 3200000
#define IN_DIM 256
#define H1 32
#define H2 64
#define WPAD 260
#define G1_ROWS 32
#define G1_SMEM ((32 * WPAD + G1_ROWS * 256) * 4)

typedef unsigned long long ull;

// ---- packed f32x2 helpers (Blackwell FFMA2: 2x fp32 FMA per issue) ---------
__device__ __forceinline__ ull ffma2(ull a, ull b, ull c) {
    ull d;
    asm("fma.rn.f32x2 %0, %1, %2, %3;" : "=l"(d) : "l"(a), "l"(b), "l"(c));
    return d;
}
__device__ __forceinline__ float2 unpack2(ull v) {
    float2 r;
    asm("mov.b64 {%0, %1}, %2;" : "=f"(r.x), "=f"(r.y) : "l"(v));
    return r;
}

// ---------------- static device scratch -------------------------------------
__device__ __align__(256) float   g_h1[NN * H1];   // x@W1 (fp32, unscaled)
__device__ __align__(256) __half2 g_h1h[NN * 16];  // scaled h1, pairs (c, c+16)
__device__ __align__(256) __half2 g_h2h[NN * 32];  // (z1@W2)*dinv, pairs (c, c+32)
__device__ int   g_cnt[NN];
__device__ int   g_rowptr[NN + 1];
__device__ int   g_pos[NN];
__device__ int   g_col[EE];
__device__ float g_dinv[NN];
__device__ int   g_bsum[256];
__device__ float g_part[2048];
__device__ float g_scalar[2];
__device__ int   g_flag;        // 1 if edge index int64, 0 if int32

// ------------- launch 0: zero counters + detect edge dtype ------------------
__global__ void detect_zero_kernel(const unsigned int* __restrict__ w, int n_vals, int N) {
    int i = blockIdx.x * blockDim.x + threadIdx.x;
    if (i < N) g_cnt[i] = 0;
    if (blockIdx.x == 0) {
        __shared__ unsigned int acc;
        if (threadIdx.x == 0) acc = 0u;
        __syncthreads();
        int K = n_vals < 2048 ? n_vals : 2048;
        unsigned int v = 0u;
        for (int j = threadIdx.x; j < K; j += blockDim.x) v |= w[2 * j + 1];
        atomicOr(&acc, v);
        __syncthreads();
        if (threadIdx.x == 0) g_flag = (acc == 0u) ? 1 : 0;
    }
}

// ------------- launch 1: histogram of dst (2 edges/thread) ------------------
__global__ void hist_kernel(const int* __restrict__ buf, int E) {
    int e = (blockIdx.x * blockDim.x + threadIdx.x) * 2;
    if (e + 1 < E) {
        int d0, d1;
        if (g_flag) { int4 v = *(const int4*)&buf[2 * (E + e)]; d0 = v.x; d1 = v.z; }
        else        { int2 v = *(const int2*)&buf[E + e];       d0 = v.x; d1 = v.y; }
        atomicAdd(&g_cnt[d0], 1);
        atomicAdd(&g_cnt[d1], 1);
    } else if (e < E) {
        int d = g_flag ? buf[2 * (E + e)] : buf[E + e];
        atomicAdd(&g_cnt[d], 1);
    }
}

__global__ void hist_kernel_s(const int* __restrict__ buf, int E) {
    int e = blockIdx.x * blockDim.x + threadIdx.x;
    if (e < E) {
        int d = g_flag ? buf[2 * (E + e)] : buf[E + e];
        atomicAdd(&g_cnt[d], 1);
    }
}

// ------------- launch 2: block scan -----------------------------------------
__global__ void scan1_kernel(int N) {
    __shared__ int sm[1024];
    int t = threadIdx.x;
    int i = blockIdx.x * 1024 + t;
    int x = (i < N) ? g_cnt[i] : 0;
    sm[t] = x;
    __syncthreads();
    for (int off = 1; off < 1024; off <<= 1) {
        int v = (t >= off) ? sm[t - off] : 0;
        __syncthreads();
        sm[t] += v;
        __syncthreads();
    }
    if (i < N) g_rowptr[i] = sm[t] - x;
    if (t == 1023) g_bsum[blockIdx.x] = sm[1023];
}

// ------------- launch 3 (PROFILED): GEMM1 via smem + FFMA2 ------------------
// 32-row x tile (66KB smem -> 3 blocks/SM), warp = 32 cols x 4 rows,
// k-packed f32x2 accumulation: 2 FFMA2 per (row, k4).
__global__ void gemm1_kernel(const float* __restrict__ x,
                             const float* __restrict__ W1, int N) {
    extern __shared__ float sm[];
    float* Wt = sm;                       // 32 * 260
    float* xs = sm + 32 * WPAD;           // 32 * 256
    int t = threadIdx.x;
    for (int i = t; i < IN_DIM * H1; i += 256) {
        int k = i >> 5, c = i & 31;
        Wt[c * WPAD + k] = W1[i];
    }
    int tile0 = blockIdx.x * G1_ROWS;
    const float4* x4 = (const float4*)x;
    float4* xsw = (float4*)xs;
    int base = tile0 * 64;
    int lim  = N * 64;
    for (int i = t; i < G1_ROWS * 64; i += 256) {
        int gi = base + i;
        xsw[i] = (gi < lim) ? x4[gi] : make_float4(0.f, 0.f, 0.f, 0.f);
    }
    __syncthreads();
    int lane = t & 31, wid = t >> 5;
    int r0 = tile0 + wid * 4;
    const ulonglong2* wrow = (const ulonglong2*)&Wt[lane * WPAD];
    const ulonglong2* xr = ((const ulonglong2*)xs) + (wid * 4) * 64;
    ull alo0 = 0, ahi0 = 0, alo1 = 0, ahi1 = 0;
    ull alo2 = 0, ahi2 = 0, alo3 = 0, ahi3 = 0;
    #pragma unroll 4
    for (int k4 = 0; k4 < 64; k4++) {
        ulonglong2 w = wrow[k4];
        ulonglong2 v0 = xr[0 * 64 + k4];
        ulonglong2 v1 = xr[1 * 64 + k4];
        ulonglong2 v2 = xr[2 * 64 + k4];
        ulonglong2 v3 = xr[3 * 64 + k4];
        alo0 = ffma2(v0.x, w.x, alo0); ahi0 = ffma2(v0.y, w.y, ahi0);
        alo1 = ffma2(v1.x, w.x, alo1); ahi1 = ffma2(v1.y, w.y, ahi1);
        alo2 = ffma2(v2.x, w.x, alo2); ahi2 = ffma2(v2.y, w.y, ahi2);
        alo3 = ffma2(v3.x, w.x, alo3); ahi3 = ffma2(v3.y, w.y, ahi3);
    }
    float2 l0 = unpack2(alo0), h0 = unpack2(ahi0);
    float2 l1 = unpack2(alo1), h1 = unpack2(ahi1);
    float2 l2 = unpack2(alo2), h2 = unpack2(ahi2);
    float2 l3 = unpack2(alo3), h3 = unpack2(ahi3);
    if (r0 + 0 < N) g_h1[(r0 + 0) * H1 + lane] = (l0.x + l0.y) + (h0.x + h0.y);
    if (r0 + 1 < N) g_h1[(r0 + 1) * H1 + lane] = (l1.x + l1.y) + (h1.x + h1.y);
    if (r0 + 2 < N) g_h1[(r0 + 2) * H1 + lane] = (l2.x + l2.y) + (h2.x + h2.y);
    if (r0 + 3 < N) g_h1[(r0 + 3) * H1 + lane] = (l3.x + l3.y) + (h3.x + h3.y);
}

// ------------- launch 4/5: scan finish + dinv + scale + fp16-pack h1 --------
__global__ void scan2_kernel(int nb) {
    if (threadIdx.x == 0 && blockIdx.x == 0) {
        int run = 0;
        for (int b = 0; b < nb; b++) { int v = g_bsum[b]; g_bsum[b] = run; run += v; }
    }
}

__global__ void scan3_kernel(int N, int E) {
    int i = blockIdx.x * blockDim.x + threadIdx.x;
    if (i < N) {
        int r = g_rowptr[i] + g_bsum[i >> 10];
        g_rowptr[i] = r;
        g_pos[i]    = r;
        float di = rsqrtf((float)(g_cnt[i] + 1));
        g_dinv[i] = di;
        float ch[32];
        const float4* h = (const float4*)&g_h1[i * H1];
        #pragma unroll
        for (int j = 0; j < 8; j++) {
            float4 v = h[j];
            ch[4 * j + 0] = v.x * di; ch[4 * j + 1] = v.y * di;
            ch[4 * j + 2] = v.z * di; ch[4 * j + 3] = v.w * di;
        }
        #pragma unroll
        for (int p = 0; p < 16; p++)
            g_h1h[i * 16 + p] = __floats2half2_rn(ch[p], ch[p + 16]);
        if (i == 0) g_rowptr[N] = E;
    }
}

// ------------- launch 6: CSR fill (2 edges/thread) --------------------------
__global__ void fill_kernel(const int* __restrict__ buf, int E) {
    int e = (blockIdx.x * blockDim.x + threadIdx.x) * 2;
    if (e + 1 < E) {
        int s0, s1, d0, d1;
        if (g_flag) {
            int4 sv = *(const int4*)&buf[2 * e];        s0 = sv.x; s1 = sv.z;
            int4 dv = *(const int4*)&buf[2 * (E + e)];  d0 = dv.x; d1 = dv.z;
        } else {
            int2 sv = *(const int2*)&buf[e];        s0 = sv.x; s1 = sv.y;
            int2 dv = *(const int2*)&buf[E + e];    d0 = dv.x; d1 = dv.y;
        }
        int p0 = atomicAdd(&g_pos[d0], 1); g_col[p0] = s0;
        int p1 = atomicAdd(&g_pos[d1], 1); g_col[p1] = s1;
    } else if (e < E) {
        int s, d;
        if (g_flag) { d = buf[2 * (E + e)]; s = buf[2 * e]; }
        else        { d = buf[E + e];       s = buf[e]; }
        int p = atomicAdd(&g_pos[d], 1);
        g_col[p] = s;
    }
}

__global__ void fill_kernel_s(const int* __restrict__ buf, int E) {
    int e = blockIdx.x * blockDim.x + threadIdx.x;
    if (e < E) {
        int s, d;
        if (g_flag) { d = buf[2 * (E + e)]; s = buf[2 * e]; }
        else        { d = buf[E + e];       s = buf[e]; }
        int p = atomicAdd(&g_pos[d], 1);
        g_col[p] = s;
    }
}

// ------------- launch 7: agg1 (fp16, 2 edges/warp-iter) + GEMV (FFMA2) ------
__global__ void agg1_gemm2_kernel(const float* __restrict__ b1,
                                  const float* __restrict__ W2, int N) {
    __shared__ float2 Wp[H1 * 32];   // Wp[k*32+c] = (W2[k][c], W2[k][c+32])
    __shared__ float2 zd[8][32];     // duplicated z pairs per warp
    int t = threadIdx.x;
    for (int i = t; i < H1 * 32; i += blockDim.x) {
        int k = i >> 5, c2 = i & 31;
        Wp[i] = make_float2(W2[k * H2 + c2], W2[k * H2 + 32 + c2]);
    }
    __syncthreads();
    int lane = t & 31, wid = t >> 5;
    int c = lane & 15;
    int hb = (lane >> 4) << 4;   // 0 or 16
    int gw = (blockIdx.x * blockDim.x + t) >> 5;
    int nw = (gridDim.x * blockDim.x) >> 5;
    float bias0 = b1[c], bias1 = b1[c + 16];
    for (int d = gw; d < N; d += nw) {
        int beg = g_rowptr[d], end = g_rowptr[d + 1];
        float aAx = 0.f, aAy = 0.f, aBx = 0.f, aBy = 0.f;
        int e = beg;
        for (; e + 32 <= end; e += 32) {
            int cv = g_col[e + lane];
            #pragma unroll
            for (int j = 0; j < 16; j += 2) {
                int s0 = __shfl_sync(0xffffffffu, cv, j + hb);
                int s1 = __shfl_sync(0xffffffffu, cv, j + 1 + hb);
                float2 f0 = __half22float2(g_h1h[s0 * 16 + c]);
                float2 f1 = __half22float2(g_h1h[s1 * 16 + c]);
                aAx += f0.x; aAy += f0.y;
                aBx += f1.x; aBy += f1.y;
            }
        }
        if (e < end) {
            int n = end - e;
            int cv = (e + lane < end) ? g_col[e + lane] : 0;
            int hodd = hb >> 4;                  // 0 or 1
            for (int j = 0; j < n; j += 2) {
                int idx = j + hodd;
                int s = __shfl_sync(0xffffffffu, cv, idx < n ? idx : 0);
                if (idx < n) {
                    float2 f = __half22float2(g_h1h[s * 16 + c]);
                    aAx += f.x; aAy += f.y;
                }
            }
        }
        float ax = aAx + aBx, ay = aAy + aBy;
        ax += __shfl_xor_sync(0xffffffffu, ax, 16);
        ay += __shfl_xor_sync(0xffffffffu, ay, 16);
        float2 sf = __half22float2(g_h1h[d * 16 + c]);   // self loop
        float di = g_dinv[d];
        float z0  = fmaxf(di * (ax + sf.x) + bias0, 0.f);   // z[c]
        float z16 = fmaxf(di * (ay + sf.y) + bias1, 0.f);   // z[c+16]
        // GEMV via smem-dup + FFMA2: h2 = (z1 @ W2) * dinv
        zd[wid][c]      = make_float2(z0, z0);
        zd[wid][c + 16] = make_float2(z16, z16);
        __syncwarp();
        ull a2 = 0;
        #pragma unroll
        for (int k = 0; k < 32; k++)
            a2 = ffma2(*(const ull*)&zd[wid][k], *(const ull*)&Wp[k * 32 + lane], a2);
        __syncwarp();
        float2 a = unpack2(a2);
        g_h2h[d * 32 + lane] = __floats2half2_rn(a.x * di, a.y * di);
    }
}

// ------------- launch 8: agg2 (fp16 gather) + MLP (smem-dup FFMA2) ----------
__global__ void agg2_mlp_kernel(const float* __restrict__ b2,
                                const float* __restrict__ Wo1, const float* __restrict__ bo1,
                                const float* __restrict__ Wo2, const float* __restrict__ bo2,
                                float* __restrict__ out, int N) {
    __shared__ float2 W1p[64 * 32];  // (Wo1[j][c], Wo1[j][c+32])
    __shared__ float2 W2p[64 * 32];
    __shared__ float2 zdup[8][64];   // duplicated activation pairs per warp
    __shared__ float2 b1p[32], b2p[32];
    __shared__ float bb[64];
    __shared__ float wsum[8];
    int t = threadIdx.x;
    for (int i = t; i < 64 * 32; i += blockDim.x) {
        int j = i >> 5, c = i & 31;
        W1p[i] = make_float2(Wo1[j * 64 + c], Wo1[j * 64 + 32 + c]);
        W2p[i] = make_float2(Wo2[j * 64 + c], Wo2[j * 64 + 32 + c]);
    }
    if (t < 32) {
        b1p[t] = make_float2(bo1[t], bo1[t + 32]);
        b2p[t] = make_float2(bo2[t], bo2[t + 32]);
    }
    if (t < 64) bb[t] = b2[t];
    __syncthreads();
    int lane = t & 31, wid = t >> 5;
    int gw = blockIdx.x * 8 + wid, nw = gridDim.x * 8;
    float bias0 = bb[lane], bias1 = bb[lane + 32];
    float ssum = 0.f;
    for (int d = gw; d < N; d += nw) {
        int beg = g_rowptr[d], end = g_rowptr[d + 1];
        float2 self = __half22float2(g_h2h[d * 32 + lane]);
        float a00 = self.x, a10 = self.y;
        float a01 = 0.f, a11 = 0.f;
        int e = beg;
        for (; e + 32 <= end; e += 32) {
            int cv = g_col[e + lane];
            #pragma unroll
            for (int j = 0; j < 32; j += 2) {
                int s0 = __shfl_sync(0xffffffffu, cv, j);
                int s1 = __shfl_sync(0xffffffffu, cv, j + 1);
                float2 f0 = __half22float2(g_h2h[s0 * 32 + lane]);
                float2 f1 = __half22float2(g_h2h[s1 * 32 + lane]);
                a00 += f0.x; a10 += f0.y;
                a01 += f1.x; a11 += f1.y;
            }
        }
        if (e < end) {
            int n = end - e;
            int cv = (e + lane < end) ? g_col[e + lane] : 0;
            for (int j = 0; j < n; j++) {
                int s = __shfl_sync(0xffffffffu, cv, j);
                float2 f = __half22float2(g_h2h[s * 32 + lane]);
                a00 += f.x; a10 += f.y;
            }
        }
        float a0 = a00 + a01, a1 = a10 + a11;
        float di = g_dinv[d];
        float t0 = fmaxf(di * a0 + bias0, 0.f);
        float t1 = fmaxf(di * a1 + bias1, 0.f);
        // layer 1: u = relu(z2 @ Wo1 + bo1)
        zdup[wid][lane]      = make_float2(t0, t0);
        zdup[wid][lane + 32] = make_float2(t1, t1);
        __syncwarp();
        ull u2 = *(const ull*)&b1p[lane];
        #pragma unroll
        for (int j = 0; j < 64; j++)
            u2 = ffma2(*(const ull*)&zdup[wid][j], *(const ull*)&W1p[j * 32 + lane], u2);
        float2 u = unpack2(u2);
        u.x = fmaxf(u.x, 0.f); u.y = fmaxf(u.y, 0.f);
        __syncwarp();
        // layer 2: l = u @ Wo2 + bo2
        zdup[wid][lane]      = make_float2(u.x, u.x);
        zdup[wid][lane + 32] = make_float2(u.y, u.y);
        __syncwarp();
        ull l2 = *(const ull*)&b2p[lane];
        #pragma unroll
        for (int j = 0; j < 64; j++)
            l2 = ffma2(*(const ull*)&zdup[wid][j], *(const ull*)&W2p[j * 32 + lane], l2);
        __syncwarp();
        float2 l = unpack2(l2);
        float e0 = __expf(l.x), e1 = __expf(l.y);
        out[d * 64 + lane]      = e0;
        out[d * 64 + 32 + lane] = e1;
        ssum += e0 + e1;
    }
    #pragma unroll
    for (int o = 16; o > 0; o >>= 1) ssum += __shfl_xor_sync(0xffffffffu, ssum, o);
    if (lane == 0) wsum[wid] = ssum;
    __syncthreads();
    if (t == 0) {
        float s = 0.f;
        #pragma unroll
        for (int i = 0; i < 8; i++) s += wsum[i];
        g_part[blockIdx.x] = s;
    }
}

// ------------- launches 9/10: finish softmax --------------------------------
__global__ void reduce_sum_kernel(int n) {
    __shared__ float ws[8];
    int t = threadIdx.x, lane = t & 31, wid = t >> 5;
    float s = 0.f;
    for (int i = t; i < n; i += blockDim.x) s += g_part[i];
    #pragma unroll
    for (int o = 16; o > 0; o >>= 1) s += __shfl_xor_sync(0xffffffffu, s, o);
    if (lane == 0) ws[wid] = s;
    __syncthreads();
    if (t == 0) {
        float r = 0.f;
        for (int i = 0; i < (int)(blockDim.x >> 5); i++) r += ws[i];
        g_scalar[1] = 1.0f / r;
    }
}

__global__ void normalize_kernel(float* __restrict__ out, int total) {
    float inv = g_scalar[1];
    int i = (blockIdx.x * blockDim.x + threadIdx.x) * 4;
    if (i + 3 < total) {
        float4 v = *(float4*)(out + i);
        v.x *= inv; v.y *= inv; v.z *= inv; v.w *= inv;
        *(float4*)(out + i) = v;
    } else {
        for (int j = i; j < total; j++) out[j] *= inv;
    }
}

// ---------------- launch ----------------------------------------------------
extern "C" void kernel_launch(void* const* d_in, const int* in_sizes, int n_in,
                              void* d_out, int out_size) {
    const float* x  = (const float*)d_in[0];
    const int*   ei = (const int*)d_in[1];
    int base = n_in - 8;   // last 8: W1,b1,W2,b2,Wo1,bo1,Wo2,bo2
    const float* W1  = (const float*)d_in[base + 0];
    const float* b1  = (const float*)d_in[base + 1];
    const float* W2  = (const float*)d_in[base + 2];
    const float* b2  = (const float*)d_in[base + 3];
    const float* Wo1 = (const float*)d_in[base + 4];
    const float* bo1 = (const float*)d_in[base + 5];
    const float* Wo2 = (const float*)d_in[base + 6];
    const float* bo2 = (const float*)d_in[base + 7];
    float* out = (float*)d_out;

    int N = in_sizes[0] / IN_DIM;
    int E = in_sizes[1] / 2;
    int nb_scan = (N + 1023) / 1024;
    bool evenE = (E % 2) == 0;

    static bool attr_set = false;
    if (!attr_set) {
        cudaFuncSetAttribute(gemm1_kernel,
                             cudaFuncAttributeMaxDynamicSharedMemorySize, G1_SMEM);
        attr_set = true;
    }

    // 0: zero cnt + dtype detect
    detect_zero_kernel<<<(N + 255) / 256, 256>>>((const unsigned int*)ei, 2 * E, N);
    // 1: histogram
    if (evenE) hist_kernel<<<(E / 2 + 255) / 256, 256>>>(ei, E);
    else       hist_kernel_s<<<(E + 255) / 256, 256>>>(ei, E);
    // 2: scan
    scan1_kernel<<<nb_scan, 1024>>>(N);
    // 3: GEMM1 (profiled slot)
    gemm1_kernel<<<(N + G1_ROWS - 1) / G1_ROWS, 256, G1_SMEM>>>(x, W1, N);
    // 4/5: scan finish + dinv + scale + fp16-pack h1
    scan2_kernel<<<1, 32>>>(nb_scan);
    scan3_kernel<<<(N + 255) / 256, 256>>>(N, E);
    // 6: CSR fill
    if (evenE) fill_kernel<<<(E / 2 + 255) / 256, 256>>>(ei, E);
    else       fill_kernel_s<<<(E + 255) / 256, 256>>>(ei, E);
    // 7: agg1 (fp16) + gemm2 (FFMA2)
    agg1_gemm2_kernel<<<2048, 256>>>(b1, W2, N);
    // 8: agg2 + MLP (FFMA2) + exp + block sums
    agg2_mlp_kernel<<<1024, 256>>>(b2, Wo1, bo1, Wo2, bo2, out, N);
    // 9/10: softmax finish
    int total = out_size;
    reduce_sum_kernel<<<1, 256>>>(1024);
    normalize_kernel<<<(total / 4 + 255) / 256, 256>>>(out, total);
}

// round 8
// speedup vs baseline: 1.2533x; 1.1869x over previous
#include <cuda_runtime.h>
#include <cuda_fp16.h>

#define NN 100000
#define EE 3200000
#define IN_DIM 256
#define H1 32
#define H2 64

typedef unsigned long long ull;

// ---- packed f32x2 helpers (Blackwell FFMA2) --------------------------------
__device__ __forceinline__ ull ffma2(ull a, ull b, ull c) {
    ull d;
    asm("fma.rn.f32x2 %0, %1, %2, %3;" : "=l"(d) : "l"(a), "l"(b), "l"(c));
    return d;
}
__device__ __forceinline__ float2 unpack2(ull v) {
    float2 r;
    asm("mov.b64 {%0, %1}, %2;" : "=f"(r.x), "=f"(r.y) : "l"(v));
    return r;
}

// ---- tf32 mma helpers -------------------------------------------------------
__device__ __forceinline__ unsigned cvt_tf32(float f) {
    unsigned u;
    asm("cvt.rna.tf32.f32 %0, %1;" : "=r"(u) : "f"(f));
    return u;
}
__device__ __forceinline__ void mma_tf32(float c[4], unsigned a0, unsigned a1,
                                         unsigned a2, unsigned a3,
                                         unsigned b0, unsigned b1) {
    asm("mma.sync.aligned.m16n8k8.row.col.f32.tf32.tf32.f32 "
        "{%0,%1,%2,%3},{%4,%5,%6,%7},{%8,%9},{%0,%1,%2,%3};"
        : "+f"(c[0]), "+f"(c[1]), "+f"(c[2]), "+f"(c[3])
        : "r"(a0), "r"(a1), "r"(a2), "r"(a3), "r"(b0), "r"(b1));
}

// ---------------- static device scratch -------------------------------------
__device__ __align__(256) float   g_h1[NN * H1];   // x@W1 (fp32, unscaled)
__device__ __align__(256) __half2 g_h1h[NN * 16];  // scaled h1, pairs (c, c+16)
__device__ __align__(256) __half2 g_h2h[NN * 32];  // (z1@W2)*dinv, pairs (c, c+32)
__device__ int   g_cnt[NN];
__device__ int   g_rowptr[NN + 1];
__device__ int   g_pos[NN];
__device__ int   g_col[EE];
__device__ float g_dinv[NN];
__device__ int   g_bsum[256];
__device__ float g_part[2048];
__device__ float g_scalar[2];
__device__ int   g_flag;        // 1 if edge index int64, 0 if int32

// ------------- launch 0: zero counters + detect edge dtype ------------------
__global__ void detect_zero_kernel(const unsigned int* __restrict__ w, int n_vals, int N) {
    int i = blockIdx.x * blockDim.x + threadIdx.x;
    if (i < N) g_cnt[i] = 0;
    if (blockIdx.x == 0) {
        __shared__ unsigned int acc;
        if (threadIdx.x == 0) acc = 0u;
        __syncthreads();
        int K = n_vals < 2048 ? n_vals : 2048;
        unsigned int v = 0u;
        for (int j = threadIdx.x; j < K; j += blockDim.x) v |= w[2 * j + 1];
        atomicOr(&acc, v);
        __syncthreads();
        if (threadIdx.x == 0) g_flag = (acc == 0u) ? 1 : 0;
    }
}

// ------------- launch 1: histogram of dst (2 edges/thread) ------------------
__global__ void hist_kernel(const int* __restrict__ buf, int E) {
    int e = (blockIdx.x * blockDim.x + threadIdx.x) * 2;
    if (e + 1 < E) {
        int d0, d1;
        if (g_flag) { int4 v = *(const int4*)&buf[2 * (E + e)]; d0 = v.x; d1 = v.z; }
        else        { int2 v = *(const int2*)&buf[E + e];       d0 = v.x; d1 = v.y; }
        atomicAdd(&g_cnt[d0], 1);
        atomicAdd(&g_cnt[d1], 1);
    } else if (e < E) {
        int d = g_flag ? buf[2 * (E + e)] : buf[E + e];
        atomicAdd(&g_cnt[d], 1);
    }
}

__global__ void hist_kernel_s(const int* __restrict__ buf, int E) {
    int e = blockIdx.x * blockDim.x + threadIdx.x;
    if (e < E) {
        int d = g_flag ? buf[2 * (E + e)] : buf[E + e];
        atomicAdd(&g_cnt[d], 1);
    }
}

// ------------- launch 2: block scan -----------------------------------------
__global__ void scan1_kernel(int N) {
    __shared__ int sm[1024];
    int t = threadIdx.x;
    int i = blockIdx.x * 1024 + t;
    int x = (i < N) ? g_cnt[i] : 0;
    sm[t] = x;
    __syncthreads();
    for (int off = 1; off < 1024; off <<= 1) {
        int v = (t >= off) ? sm[t - off] : 0;
        __syncthreads();
        sm[t] += v;
        __syncthreads();
    }
    if (i < N) g_rowptr[i] = sm[t] - x;
    if (t == 1023) g_bsum[blockIdx.x] = sm[1023];
}

// ------------- launch 3 (PROFILED): GEMM1 via tf32 tensor cores -------------
// Warp = 32 rows (2x m16n32k256 tiles sharing B regs). A straight from global
// (L1-resident across k-steps); B staged fragment-contiguous (conflict-free).
__global__ void gemm1_kernel(const float* __restrict__ x,
                             const float* __restrict__ W1, int N) {
    __shared__ unsigned Bs[8192];   // [ks][nf][j][lane], 32 KB
    int t = threadIdx.x;
    for (int i = t; i < 8192; i += 256) {
        int lane2 = i & 31;
        int j  = (i >> 5) & 1;
        int nf = (i >> 6) & 3;
        int ks = i >> 8;
        int k = ks * 8 + (lane2 & 3) + j * 4;
        int n = nf * 8 + (lane2 >> 2);
        Bs[i] = cvt_tf32(W1[k * 32 + n]);
    }
    __syncthreads();
    int lane = t & 31, wid = t >> 5;
    int qrow = lane >> 2, qk = lane & 3;
    long r0 = (long)(blockIdx.x * 8 + wid) * 32;
    if (r0 >= N) return;
    long NL = N - 1;
    const float* p0 = x + (r0 + qrow      <= NL ? r0 + qrow      : NL) * 256 + qk;
    const float* p1 = x + (r0 + qrow + 8  <= NL ? r0 + qrow + 8  : NL) * 256 + qk;
    const float* p2 = x + (r0 + qrow + 16 <= NL ? r0 + qrow + 16 : NL) * 256 + qk;
    const float* p3 = x + (r0 + qrow + 24 <= NL ? r0 + qrow + 24 : NL) * 256 + qk;
    float c0[4][4] = {}, c1[4][4] = {};
    #pragma unroll 4
    for (int ks = 0; ks < 32; ks++) {
        int k0 = ks * 8;
        const unsigned* bp = &Bs[ks * 256 + lane];
        unsigned b00 = bp[0],   b01 = bp[32];
        unsigned b10 = bp[64],  b11 = bp[96];
        unsigned b20 = bp[128], b21 = bp[160];
        unsigned b30 = bp[192], b31 = bp[224];
        unsigned a0 = cvt_tf32(p0[k0]);
        unsigned a1 = cvt_tf32(p1[k0]);
        unsigned a2 = cvt_tf32(p0[k0 + 4]);
        unsigned a3 = cvt_tf32(p1[k0 + 4]);
        mma_tf32(c0[0], a0, a1, a2, a3, b00, b01);
        mma_tf32(c0[1], a0, a1, a2, a3, b10, b11);
        mma_tf32(c0[2], a0, a1, a2, a3, b20, b21);
        mma_tf32(c0[3], a0, a1, a2, a3, b30, b31);
        a0 = cvt_tf32(p2[k0]);
        a1 = cvt_tf32(p3[k0]);
        a2 = cvt_tf32(p2[k0 + 4]);
        a3 = cvt_tf32(p3[k0 + 4]);
        mma_tf32(c1[0], a0, a1, a2, a3, b00, b01);
        mma_tf32(c1[1], a0, a1, a2, a3, b10, b11);
        mma_tf32(c1[2], a0, a1, a2, a3, b20, b21);
        mma_tf32(c1[3], a0, a1, a2, a3, b30, b31);
    }
    long rw0 = r0 + qrow, rw1 = rw0 + 8, rw2 = rw0 + 16, rw3 = rw0 + 24;
    int cb = 2 * qk;
    #pragma unroll
    for (int nf = 0; nf < 4; nf++) {
        int col = nf * 8 + cb;
        if (rw0 < N) *(float2*)&g_h1[rw0 * 32 + col] = make_float2(c0[nf][0], c0[nf][1]);
        if (rw1 < N) *(float2*)&g_h1[rw1 * 32 + col] = make_float2(c0[nf][2], c0[nf][3]);
        if (rw2 < N) *(float2*)&g_h1[rw2 * 32 + col] = make_float2(c1[nf][0], c1[nf][1]);
        if (rw3 < N) *(float2*)&g_h1[rw3 * 32 + col] = make_float2(c1[nf][2], c1[nf][3]);
    }
}

// ------------- launch 4/5: scan finish + dinv + scale + fp16-pack h1 --------
__global__ void scan2_kernel(int nb) {
    if (threadIdx.x == 0 && blockIdx.x == 0) {
        int run = 0;
        for (int b = 0; b < nb; b++) { int v = g_bsum[b]; g_bsum[b] = run; run += v; }
    }
}

__global__ void scan3_kernel(int N, int E) {
    int i = blockIdx.x * blockDim.x + threadIdx.x;
    if (i < N) {
        int r = g_rowptr[i] + g_bsum[i >> 10];
        g_rowptr[i] = r;
        g_pos[i]    = r;
        float di = rsqrtf((float)(g_cnt[i] + 1));
        g_dinv[i] = di;
        float ch[32];
        const float4* h = (const float4*)&g_h1[i * H1];
        #pragma unroll
        for (int j = 0; j < 8; j++) {
            float4 v = h[j];
            ch[4 * j + 0] = v.x * di; ch[4 * j + 1] = v.y * di;
            ch[4 * j + 2] = v.z * di; ch[4 * j + 3] = v.w * di;
        }
        #pragma unroll
        for (int p = 0; p < 16; p++)
            g_h1h[i * 16 + p] = __floats2half2_rn(ch[p], ch[p + 16]);
        if (i == 0) g_rowptr[N] = E;
    }
}

// ------------- launch 6: CSR fill (2 edges/thread) --------------------------
__global__ void fill_kernel(const int* __restrict__ buf, int E) {
    int e = (blockIdx.x * blockDim.x + threadIdx.x) * 2;
    if (e + 1 < E) {
        int s0, s1, d0, d1;
        if (g_flag) {
            int4 sv = *(const int4*)&buf[2 * e];        s0 = sv.x; s1 = sv.z;
            int4 dv = *(const int4*)&buf[2 * (E + e)];  d0 = dv.x; d1 = dv.z;
        } else {
            int2 sv = *(const int2*)&buf[e];        s0 = sv.x; s1 = sv.y;
            int2 dv = *(const int2*)&buf[E + e];    d0 = dv.x; d1 = dv.y;
        }
        int p0 = atomicAdd(&g_pos[d0], 1); g_col[p0] = s0;
        int p1 = atomicAdd(&g_pos[d1], 1); g_col[p1] = s1;
    } else if (e < E) {
        int s, d;
        if (g_flag) { d = buf[2 * (E + e)]; s = buf[2 * e]; }
        else        { d = buf[E + e];       s = buf[e]; }
        int p = atomicAdd(&g_pos[d], 1);
        g_col[p] = s;
    }
}

__global__ void fill_kernel_s(const int* __restrict__ buf, int E) {
    int e = blockIdx.x * blockDim.x + threadIdx.x;
    if (e < E) {
        int s, d;
        if (g_flag) { d = buf[2 * (E + e)]; s = buf[2 * e]; }
        else        { d = buf[E + e];       s = buf[e]; }
        int p = atomicAdd(&g_pos[d], 1);
        g_col[p] = s;
    }
}

// ------------- launch 7: agg1 (fp16, 2 edges/warp-iter) + GEMV (FFMA2) ------
__global__ void agg1_gemm2_kernel(const float* __restrict__ b1,
                                  const float* __restrict__ W2, int N) {
    __shared__ float2 Wp[H1 * 32];   // Wp[k*32+c] = (W2[k][c], W2[k][c+32])
    __shared__ float2 zd[8][32];     // duplicated z pairs per warp
    int t = threadIdx.x;
    for (int i = t; i < H1 * 32; i += blockDim.x) {
        int k = i >> 5, c2 = i & 31;
        Wp[i] = make_float2(W2[k * H2 + c2], W2[k * H2 + 32 + c2]);
    }
    __syncthreads();
    int lane = t & 31, wid = t >> 5;
    int c = lane & 15;
    int hb = (lane >> 4) << 4;   // 0 or 16
    int gw = (blockIdx.x * blockDim.x + t) >> 5;
    int nw = (gridDim.x * blockDim.x) >> 5;
    float bias0 = b1[c], bias1 = b1[c + 16];
    for (int d = gw; d < N; d += nw) {
        int beg = g_rowptr[d], end = g_rowptr[d + 1];
        float aAx = 0.f, aAy = 0.f, aBx = 0.f, aBy = 0.f;
        int e = beg;
        for (; e + 32 <= end; e += 32) {
            int cv = g_col[e + lane];
            #pragma unroll
            for (int j = 0; j < 16; j += 2) {
                int s0 = __shfl_sync(0xffffffffu, cv, j + hb);
                int s1 = __shfl_sync(0xffffffffu, cv, j + 1 + hb);
                float2 f0 = __half22float2(g_h1h[s0 * 16 + c]);
                float2 f1 = __half22float2(g_h1h[s1 * 16 + c]);
                aAx += f0.x; aAy += f0.y;
                aBx += f1.x; aBy += f1.y;
            }
        }
        if (e < end) {
            int n = end - e;
            int cv = (e + lane < end) ? g_col[e + lane] : 0;
            int hodd = hb >> 4;                  // 0 or 1
            for (int j = 0; j < n; j += 2) {
                int idx = j + hodd;
                int s = __shfl_sync(0xffffffffu, cv, idx < n ? idx : 0);
                if (idx < n) {
                    float2 f = __half22float2(g_h1h[s * 16 + c]);
                    aAx += f.x; aAy += f.y;
                }
            }
        }
        float ax = aAx + aBx, ay = aAy + aBy;
        ax += __shfl_xor_sync(0xffffffffu, ax, 16);
        ay += __shfl_xor_sync(0xffffffffu, ay, 16);
        float2 sf = __half22float2(g_h1h[d * 16 + c]);   // self loop
        float di = g_dinv[d];
        float z0  = fmaxf(di * (ax + sf.x) + bias0, 0.f);   // z[c]
        float z16 = fmaxf(di * (ay + sf.y) + bias1, 0.f);   // z[c+16]
        zd[wid][c]      = make_float2(z0, z0);
        zd[wid][c + 16] = make_float2(z16, z16);
        __syncwarp();
        ull a2 = 0;
        #pragma unroll
        for (int k = 0; k < 32; k++)
            a2 = ffma2(*(const ull*)&zd[wid][k], *(const ull*)&Wp[k * 32 + lane], a2);
        __syncwarp();
        float2 a = unpack2(a2);
        g_h2h[d * 32 + lane] = __floats2half2_rn(a.x * di, a.y * di);
    }
}

// ------------- launch 8: agg2 (fp16 gather) + MLP (smem-dup FFMA2) ----------
__global__ void agg2_mlp_kernel(const float* __restrict__ b2,
                                const float* __restrict__ Wo1, const float* __restrict__ bo1,
                                const float* __restrict__ Wo2, const float* __restrict__ bo2,
                                float* __restrict__ out, int N) {
    __shared__ float2 W1p[64 * 32];  // (Wo1[j][c], Wo1[j][c+32])
    __shared__ float2 W2p[64 * 32];
    __shared__ float2 zdup[8][64];   // duplicated activation pairs per warp
    __shared__ float2 b1p[32], b2p[32];
    __shared__ float bb[64];
    __shared__ float wsum[8];
    int t = threadIdx.x;
    for (int i = t; i < 64 * 32; i += blockDim.x) {
        int j = i >> 5, c = i & 31;
        W1p[i] = make_float2(Wo1[j * 64 + c], Wo1[j * 64 + 32 + c]);
        W2p[i] = make_float2(Wo2[j * 64 + c], Wo2[j * 64 + 32 + c]);
    }
    if (t < 32) {
        b1p[t] = make_float2(bo1[t], bo1[t + 32]);
        b2p[t] = make_float2(bo2[t], bo2[t + 32]);
    }
    if (t < 64) bb[t] = b2[t];
    __syncthreads();
    int lane = t & 31, wid = t >> 5;
    int gw = blockIdx.x * 8 + wid, nw = gridDim.x * 8;
    float bias0 = bb[lane], bias1 = bb[lane + 32];
    float ssum = 0.f;
    for (int d = gw; d < N; d += nw) {
        int beg = g_rowptr[d], end = g_rowptr[d + 1];
        float2 self = __half22float2(g_h2h[d * 32 + lane]);
        float a00 = self.x, a10 = self.y;
        float a01 = 0.f, a11 = 0.f;
        int e = beg;
        for (; e + 32 <= end; e += 32) {
            int cv = g_col[e + lane];
            #pragma unroll
            for (int j = 0; j < 32; j += 2) {
                int s0 = __shfl_sync(0xffffffffu, cv, j);
                int s1 = __shfl_sync(0xffffffffu, cv, j + 1);
                float2 f0 = __half22float2(g_h2h[s0 * 32 + lane]);
                float2 f1 = __half22float2(g_h2h[s1 * 32 + lane]);
                a00 += f0.x; a10 += f0.y;
                a01 += f1.x; a11 += f1.y;
            }
        }
        if (e < end) {
            int n = end - e;
            int cv = (e + lane < end) ? g_col[e + lane] : 0;
            for (int j = 0; j < n; j++) {
                int s = __shfl_sync(0xffffffffu, cv, j);
                float2 f = __half22float2(g_h2h[s * 32 + lane]);
                a00 += f.x; a10 += f.y;
            }
        }
        float a0 = a00 + a01, a1 = a10 + a11;
        float di = g_dinv[d];
        float t0 = fmaxf(di * a0 + bias0, 0.f);
        float t1 = fmaxf(di * a1 + bias1, 0.f);
        // layer 1: u = relu(z2 @ Wo1 + bo1)
        zdup[wid][lane]      = make_float2(t0, t0);
        zdup[wid][lane + 32] = make_float2(t1, t1);
        __syncwarp();
        ull u2 = *(const ull*)&b1p[lane];
        #pragma unroll
        for (int j = 0; j < 64; j++)
            u2 = ffma2(*(const ull*)&zdup[wid][j], *(const ull*)&W1p[j * 32 + lane], u2);
        float2 u = unpack2(u2);
        u.x = fmaxf(u.x, 0.f); u.y = fmaxf(u.y, 0.f);
        __syncwarp();
        // layer 2: l = u @ Wo2 + bo2
        zdup[wid][lane]      = make_float2(u.x, u.x);
        zdup[wid][lane + 32] = make_float2(u.y, u.y);
        __syncwarp();
        ull l2 = *(const ull*)&b2p[lane];
        #pragma unroll
        for (int j = 0; j < 64; j++)
            l2 = ffma2(*(const ull*)&zdup[wid][j], *(const ull*)&W2p[j * 32 + lane], l2);
        __syncwarp();
        float2 l = unpack2(l2);
        float e0 = __expf(l.x), e1 = __expf(l.y);
        out[d * 64 + lane]      = e0;
        out[d * 64 + 32 + lane] = e1;
        ssum += e0 + e1;
    }
    #pragma unroll
    for (int o = 16; o > 0; o >>= 1) ssum += __shfl_xor_sync(0xffffffffu, ssum, o);
    if (lane == 0) wsum[wid] = ssum;
    __syncthreads();
    if (t == 0) {
        float s = 0.f;
        #pragma unroll
        for (int i = 0; i < 8; i++) s += wsum[i];
        g_part[blockIdx.x] = s;
    }
}

// ------------- launches 9/10: finish softmax --------------------------------
__global__ void reduce_sum_kernel(int n) {
    __shared__ float ws[8];
    int t = threadIdx.x, lane = t & 31, wid = t >> 5;
    float s = 0.f;
    for (int i = t; i < n; i += blockDim.x) s += g_part[i];
    #pragma unroll
    for (int o = 16; o > 0; o >>= 1) s += __shfl_xor_sync(0xffffffffu, s, o);
    if (lane == 0) ws[wid] = s;
    __syncthreads();
    if (t == 0) {
        float r = 0.f;
        for (int i = 0; i < (int)(blockDim.x >> 5); i++) r += ws[i];
        g_scalar[1] = 1.0f / r;
    }
}

__global__ void normalize_kernel(float* __restrict__ out, int total) {
    float inv = g_scalar[1];
    int i = (blockIdx.x * blockDim.x + threadIdx.x) * 4;
    if (i + 3 < total) {
        float4 v = *(float4*)(out + i);
        v.x *= inv; v.y *= inv; v.z *= inv; v.w *= inv;
        *(float4*)(out + i) = v;
    } else {
        for (int j = i; j < total; j++) out[j] *= inv;
    }
}

// ---------------- launch ----------------------------------------------------
extern "C" void kernel_launch(void* const* d_in, const int* in_sizes, int n_in,
                              void* d_out, int out_size) {
    const float* x  = (const float*)d_in[0];
    const int*   ei = (const int*)d_in[1];
    int base = n_in - 8;   // last 8: W1,b1,W2,b2,Wo1,bo1,Wo2,bo2
    const float* W1  = (const float*)d_in[base + 0];
    const float* b1  = (const float*)d_in[base + 1];
    const float* W2  = (const float*)d_in[base + 2];
    const float* b2  = (const float*)d_in[base + 3];
    const float* Wo1 = (const float*)d_in[base + 4];
    const float* bo1 = (const float*)d_in[base + 5];
    const float* Wo2 = (const float*)d_in[base + 6];
    const float* bo2 = (const float*)d_in[base + 7];
    float* out = (float*)d_out;

    int N = in_sizes[0] / IN_DIM;
    int E = in_sizes[1] / 2;
    int nb_scan = (N + 1023) / 1024;
    bool evenE = (E % 2) == 0;

    // 0: zero cnt + dtype detect
    detect_zero_kernel<<<(N + 255) / 256, 256>>>((const unsigned int*)ei, 2 * E, N);
    // 1: histogram
    if (evenE) hist_kernel<<<(E / 2 + 255) / 256, 256>>>(ei, E);
    else       hist_kernel_s<<<(E + 255) / 256, 256>>>(ei, E);
    // 2: scan
    scan1_kernel<<<nb_scan, 1024>>>(N);
    // 3: GEMM1 tf32 tensor cores (profiled slot)
    int nWarpTiles = (N + 31) / 32;
    gemm1_kernel<<<(nWarpTiles + 7) / 8, 256>>>(x, W1, N);
    // 4/5: scan finish + dinv + scale + fp16-pack h1
    scan2_kernel<<<1, 32>>>(nb_scan);
    scan3_kernel<<<(N + 255) / 256, 256>>>(N, E);
    // 6: CSR fill
    if (evenE) fill_kernel<<<(E / 2 + 255) / 256, 256>>>(ei, E);
    else       fill_kernel_s<<<(E + 255) / 256, 256>>>(ei, E);
    // 7: agg1 (fp16) + gemm2 (FFMA2)
    agg1_gemm2_kernel<<<2048, 256>>>(b1, W2, N);
    // 8: agg2 + MLP (FFMA2) + exp + block sums
    agg2_mlp_kernel<<<1024, 256>>>(b2, Wo1, bo1, Wo2, bo2, out, N);
    // 9/10: softmax finish
    int total = out_size;
    reduce_sum_kernel<<<1, 256>>>(1024);
    normalize_kernel<<<(total / 4 + 255) / 256, 256>>>(out, total);
}

// round 9
// speedup vs baseline: 1.3841x; 1.1044x over previous
#include <cuda_runtime.h>
#include <cuda_fp16.h>

#define NN 100000
#define EE 3200000
#define IN_DIM 256
#define H1 32
#define H2 64

typedef unsigned long long ull;

// ---- packed f32x2 helpers (Blackwell FFMA2) --------------------------------
__device__ __forceinline__ ull ffma2(ull a, ull b, ull c) {
    ull d;
    asm("fma.rn.f32x2 %0, %1, %2, %3;" : "=l"(d) : "l"(a), "l"(b), "l"(c));
    return d;
}
__device__ __forceinline__ float2 unpack2(ull v) {
    float2 r;
    asm("mov.b64 {%0, %1}, %2;" : "=f"(r.x), "=f"(r.y) : "l"(v));
    return r;
}

// ---- tf32 mma helpers -------------------------------------------------------
__device__ __forceinline__ unsigned cvt_tf32(float f) {
    unsigned u;
    asm("cvt.rna.tf32.f32 %0, %1;" : "=r"(u) : "f"(f));
    return u;
}
__device__ __forceinline__ void mma_tf32(float c[4], unsigned a0, unsigned a1,
                                         unsigned a2, unsigned a3,
                                         unsigned b0, unsigned b1) {
    asm("mma.sync.aligned.m16n8k8.row.col.f32.tf32.tf32.f32 "
        "{%0,%1,%2,%3},{%4,%5,%6,%7},{%8,%9},{%0,%1,%2,%3};"
        : "+f"(c[0]), "+f"(c[1]), "+f"(c[2]), "+f"(c[3])
        : "r"(a0), "r"(a1), "r"(a2), "r"(a3), "r"(b0), "r"(b1));
}

// ---------------- static device scratch -------------------------------------
__device__ __align__(256) float   g_h1[NN * H1];   // x@W1 (fp32, unscaled)
__device__ __align__(256) __half2 g_h1h[NN * 16];  // scaled h1, pairs (c, c+16)
__device__ __align__(256) __half2 g_h2h[NN * 32];  // (z1@W2)*dinv, pairs (c, c+32)
__device__ int   g_cnt[NN];
__device__ int   g_rowptr[NN + 1];
__device__ int   g_pos[NN];
__device__ int   g_col[EE];
__device__ float g_dinv[NN];
__device__ int   g_bsum[256];
__device__ float g_part[2048];
__device__ float g_scalar[2];
__device__ int   g_flag;        // 1 if edge index int64, 0 if int32

// ------------- zero counters + detect edge dtype ----------------------------
__global__ void detect_zero_kernel(const unsigned int* __restrict__ w, int n_vals, int N) {
    int i = blockIdx.x * blockDim.x + threadIdx.x;
    if (i < N) g_cnt[i] = 0;
    if (blockIdx.x == 0) {
        __shared__ unsigned int acc;
        if (threadIdx.x == 0) acc = 0u;
        __syncthreads();
        int K = n_vals < 2048 ? n_vals : 2048;
        unsigned int v = 0u;
        for (int j = threadIdx.x; j < K; j += blockDim.x) v |= w[2 * j + 1];
        atomicOr(&acc, v);
        __syncthreads();
        if (threadIdx.x == 0) g_flag = (acc == 0u) ? 1 : 0;
    }
}

// ------------- histogram of dst (2 edges/thread) ----------------------------
__global__ void hist_kernel(const int* __restrict__ buf, int E) {
    int e = (blockIdx.x * blockDim.x + threadIdx.x) * 2;
    if (e + 1 < E) {
        int d0, d1;
        if (g_flag) { int4 v = *(const int4*)&buf[2 * (E + e)]; d0 = v.x; d1 = v.z; }
        else        { int2 v = *(const int2*)&buf[E + e];       d0 = v.x; d1 = v.y; }
        atomicAdd(&g_cnt[d0], 1);
        atomicAdd(&g_cnt[d1], 1);
    } else if (e < E) {
        int d = g_flag ? buf[2 * (E + e)] : buf[E + e];
        atomicAdd(&g_cnt[d], 1);
    }
}

__global__ void hist_kernel_s(const int* __restrict__ buf, int E) {
    int e = blockIdx.x * blockDim.x + threadIdx.x;
    if (e < E) {
        int d = g_flag ? buf[2 * (E + e)] : buf[E + e];
        atomicAdd(&g_cnt[d], 1);
    }
}

// ------------- block scan -----------------------------------------------------
__global__ void scan1_kernel(int N) {
    __shared__ int sm[1024];
    int t = threadIdx.x;
    int i = blockIdx.x * 1024 + t;
    int x = (i < N) ? g_cnt[i] : 0;
    sm[t] = x;
    __syncthreads();
    for (int off = 1; off < 1024; off <<= 1) {
        int v = (t >= off) ? sm[t - off] : 0;
        __syncthreads();
        sm[t] += v;
        __syncthreads();
    }
    if (i < N) g_rowptr[i] = sm[t] - x;
    if (t == 1023) g_bsum[blockIdx.x] = sm[1023];
}

__global__ void scan2_kernel(int nb) {
    if (threadIdx.x == 0 && blockIdx.x == 0) {
        int run = 0;
        for (int b = 0; b < nb; b++) { int v = g_bsum[b]; g_bsum[b] = run; run += v; }
    }
}

// scan3a: finalize rowptr/pos/dinv only (independent of gemm1)
__global__ void scan3a_kernel(int N, int E) {
    int i = blockIdx.x * blockDim.x + threadIdx.x;
    if (i < N) {
        int r = g_rowptr[i] + g_bsum[i >> 10];
        g_rowptr[i] = r;
        g_pos[i]    = r;
        g_dinv[i]   = rsqrtf((float)(g_cnt[i] + 1));
        if (i == 0) g_rowptr[N] = E;
    }
}

// pack_h1: scale by dinv and pack to fp16 pairs (needs gemm1 + scan3a)
__global__ void pack_h1_kernel(int N) {
    int i = blockIdx.x * blockDim.x + threadIdx.x;
    if (i < N) {
        float di = g_dinv[i];
        float ch[32];
        const float4* h = (const float4*)&g_h1[i * H1];
        #pragma unroll
        for (int j = 0; j < 8; j++) {
            float4 v = h[j];
            ch[4 * j + 0] = v.x * di; ch[4 * j + 1] = v.y * di;
            ch[4 * j + 2] = v.z * di; ch[4 * j + 3] = v.w * di;
        }
        #pragma unroll
        for (int p = 0; p < 16; p++)
            g_h1h[i * 16 + p] = __floats2half2_rn(ch[p], ch[p + 16]);
    }
}

// ------------- GEMM1 via tf32 tensor cores (runs on side stream) ------------
__global__ void gemm1_kernel(const float* __restrict__ x,
                             const float* __restrict__ W1, int N) {
    __shared__ unsigned Bs[8192];   // [ks][nf][j][lane], 32 KB
    int t = threadIdx.x;
    for (int i = t; i < 8192; i += 256) {
        int lane2 = i & 31;
        int j  = (i >> 5) & 1;
        int nf = (i >> 6) & 3;
        int ks = i >> 8;
        int k = ks * 8 + (lane2 & 3) + j * 4;
        int n = nf * 8 + (lane2 >> 2);
        Bs[i] = cvt_tf32(W1[k * 32 + n]);
    }
    __syncthreads();
    int lane = t & 31, wid = t >> 5;
    int qrow = lane >> 2, qk = lane & 3;
    long r0 = (long)(blockIdx.x * 8 + wid) * 32;
    if (r0 >= N) return;
    long NL = N - 1;
    const float* p0 = x + (r0 + qrow      <= NL ? r0 + qrow      : NL) * 256 + qk;
    const float* p1 = x + (r0 + qrow + 8  <= NL ? r0 + qrow + 8  : NL) * 256 + qk;
    const float* p2 = x + (r0 + qrow + 16 <= NL ? r0 + qrow + 16 : NL) * 256 + qk;
    const float* p3 = x + (r0 + qrow + 24 <= NL ? r0 + qrow + 24 : NL) * 256 + qk;
    float c0[4][4] = {}, c1[4][4] = {};
    #pragma unroll 4
    for (int ks = 0; ks < 32; ks++) {
        int k0 = ks * 8;
        const unsigned* bp = &Bs[ks * 256 + lane];
        unsigned b00 = bp[0],   b01 = bp[32];
        unsigned b10 = bp[64],  b11 = bp[96];
        unsigned b20 = bp[128], b21 = bp[160];
        unsigned b30 = bp[192], b31 = bp[224];
        unsigned a0 = cvt_tf32(p0[k0]);
        unsigned a1 = cvt_tf32(p1[k0]);
        unsigned a2 = cvt_tf32(p0[k0 + 4]);
        unsigned a3 = cvt_tf32(p1[k0 + 4]);
        mma_tf32(c0[0], a0, a1, a2, a3, b00, b01);
        mma_tf32(c0[1], a0, a1, a2, a3, b10, b11);
        mma_tf32(c0[2], a0, a1, a2, a3, b20, b21);
        mma_tf32(c0[3], a0, a1, a2, a3, b30, b31);
        a0 = cvt_tf32(p2[k0]);
        a1 = cvt_tf32(p3[k0]);
        a2 = cvt_tf32(p2[k0 + 4]);
        a3 = cvt_tf32(p3[k0 + 4]);
        mma_tf32(c1[0], a0, a1, a2, a3, b00, b01);
        mma_tf32(c1[1], a0, a1, a2, a3, b10, b11);
        mma_tf32(c1[2], a0, a1, a2, a3, b20, b21);
        mma_tf32(c1[3], a0, a1, a2, a3, b30, b31);
    }
    long rw0 = r0 + qrow, rw1 = rw0 + 8, rw2 = rw0 + 16, rw3 = rw0 + 24;
    int cb = 2 * qk;
    #pragma unroll
    for (int nf = 0; nf < 4; nf++) {
        int col = nf * 8 + cb;
        if (rw0 < N) *(float2*)&g_h1[rw0 * 32 + col] = make_float2(c0[nf][0], c0[nf][1]);
        if (rw1 < N) *(float2*)&g_h1[rw1 * 32 + col] = make_float2(c0[nf][2], c0[nf][3]);
        if (rw2 < N) *(float2*)&g_h1[rw2 * 32 + col] = make_float2(c1[nf][0], c1[nf][1]);
        if (rw3 < N) *(float2*)&g_h1[rw3 * 32 + col] = make_float2(c1[nf][2], c1[nf][3]);
    }
}

// ------------- CSR fill (2 edges/thread) ------------------------------------
__global__ void fill_kernel(const int* __restrict__ buf, int E) {
    int e = (blockIdx.x * blockDim.x + threadIdx.x) * 2;
    if (e + 1 < E) {
        int s0, s1, d0, d1;
        if (g_flag) {
            int4 sv = *(const int4*)&buf[2 * e];        s0 = sv.x; s1 = sv.z;
            int4 dv = *(const int4*)&buf[2 * (E + e)];  d0 = dv.x; d1 = dv.z;
        } else {
            int2 sv = *(const int2*)&buf[e];        s0 = sv.x; s1 = sv.y;
            int2 dv = *(const int2*)&buf[E + e];    d0 = dv.x; d1 = dv.y;
        }
        int p0 = atomicAdd(&g_pos[d0], 1); g_col[p0] = s0;
        int p1 = atomicAdd(&g_pos[d1], 1); g_col[p1] = s1;
    } else if (e < E) {
        int s, d;
        if (g_flag) { d = buf[2 * (E + e)]; s = buf[2 * e]; }
        else        { d = buf[E + e];       s = buf[e]; }
        int p = atomicAdd(&g_pos[d], 1);
        g_col[p] = s;
    }
}

__global__ void fill_kernel_s(const int* __restrict__ buf, int E) {
    int e = blockIdx.x * blockDim.x + threadIdx.x;
    if (e < E) {
        int s, d;
        if (g_flag) { d = buf[2 * (E + e)]; s = buf[2 * e]; }
        else        { d = buf[E + e];       s = buf[e]; }
        int p = atomicAdd(&g_pos[d], 1);
        g_col[p] = s;
    }
}

// ------------- agg1 (fp16, 2 edges/warp-iter) + GEMV (FFMA2) ----------------
__global__ void agg1_gemm2_kernel(const float* __restrict__ b1,
                                  const float* __restrict__ W2, int N) {
    __shared__ float2 Wp[H1 * 32];   // Wp[k*32+c] = (W2[k][c], W2[k][c+32])
    __shared__ float2 zd[8][32];     // duplicated z pairs per warp
    int t = threadIdx.x;
    for (int i = t; i < H1 * 32; i += blockDim.x) {
        int k = i >> 5, c2 = i & 31;
        Wp[i] = make_float2(W2[k * H2 + c2], W2[k * H2 + 32 + c2]);
    }
    __syncthreads();
    int lane = t & 31, wid = t >> 5;
    int c = lane & 15;
    int hb = (lane >> 4) << 4;   // 0 or 16
    int gw = (blockIdx.x * blockDim.x + t) >> 5;
    int nw = (gridDim.x * blockDim.x) >> 5;
    float bias0 = b1[c], bias1 = b1[c + 16];
    for (int d = gw; d < N; d += nw) {
        int beg = g_rowptr[d], end = g_rowptr[d + 1];
        float aAx = 0.f, aAy = 0.f, aBx = 0.f, aBy = 0.f;
        int e = beg;
        for (; e + 32 <= end; e += 32) {
            int cv = g_col[e + lane];
            #pragma unroll
            for (int j = 0; j < 16; j += 2) {
                int s0 = __shfl_sync(0xffffffffu, cv, j + hb);
                int s1 = __shfl_sync(0xffffffffu, cv, j + 1 + hb);
                float2 f0 = __half22float2(g_h1h[s0 * 16 + c]);
                float2 f1 = __half22float2(g_h1h[s1 * 16 + c]);
                aAx += f0.x; aAy += f0.y;
                aBx += f1.x; aBy += f1.y;
            }
        }
        if (e < end) {
            int n = end - e;
            int cv = (e + lane < end) ? g_col[e + lane] : 0;
            int hodd = hb >> 4;                  // 0 or 1
            for (int j = 0; j < n; j += 2) {
                int idx = j + hodd;
                int s = __shfl_sync(0xffffffffu, cv, idx < n ? idx : 0);
                if (idx < n) {
                    float2 f = __half22float2(g_h1h[s * 16 + c]);
                    aAx += f.x; aAy += f.y;
                }
            }
        }
        float ax = aAx + aBx, ay = aAy + aBy;
        ax += __shfl_xor_sync(0xffffffffu, ax, 16);
        ay += __shfl_xor_sync(0xffffffffu, ay, 16);
        float2 sf = __half22float2(g_h1h[d * 16 + c]);   // self loop
        float di = g_dinv[d];
        float z0  = fmaxf(di * (ax + sf.x) + bias0, 0.f);   // z[c]
        float z16 = fmaxf(di * (ay + sf.y) + bias1, 0.f);   // z[c+16]
        zd[wid][c]      = make_float2(z0, z0);
        zd[wid][c + 16] = make_float2(z16, z16);
        __syncwarp();
        ull a2 = 0;
        #pragma unroll
        for (int k = 0; k < 32; k++)
            a2 = ffma2(*(const ull*)&zd[wid][k], *(const ull*)&Wp[k * 32 + lane], a2);
        __syncwarp();
        float2 a = unpack2(a2);
        g_h2h[d * 32 + lane] = __floats2half2_rn(a.x * di, a.y * di);
    }
}

// ------------- agg2 (fp16 gather) + MLP (smem-dup FFMA2) --------------------
__global__ void agg2_mlp_kernel(const float* __restrict__ b2,
                                const float* __restrict__ Wo1, const float* __restrict__ bo1,
                                const float* __restrict__ Wo2, const float* __restrict__ bo2,
                                float* __restrict__ out, int N) {
    __shared__ float2 W1p[64 * 32];  // (Wo1[j][c], Wo1[j][c+32])
    __shared__ float2 W2p[64 * 32];
    __shared__ float2 zdup[8][64];   // duplicated activation pairs per warp
    __shared__ float2 b1p[32], b2p[32];
    __shared__ float bb[64];
    __shared__ float wsum[8];
    int t = threadIdx.x;
    for (int i = t; i < 64 * 32; i += blockDim.x) {
        int j = i >> 5, c = i & 31;
        W1p[i] = make_float2(Wo1[j * 64 + c], Wo1[j * 64 + 32 + c]);
        W2p[i] = make_float2(Wo2[j * 64 + c], Wo2[j * 64 + 32 + c]);
    }
    if (t < 32) {
        b1p[t] = make_float2(bo1[t], bo1[t + 32]);
        b2p[t] = make_float2(bo2[t], bo2[t + 32]);
    }
    if (t < 64) bb[t] = b2[t];
    __syncthreads();
    int lane = t & 31, wid = t >> 5;
    int gw = blockIdx.x * 8 + wid, nw = gridDim.x * 8;
    float bias0 = bb[lane], bias1 = bb[lane + 32];
    float ssum = 0.f;
    for (int d = gw; d < N; d += nw) {
        int beg = g_rowptr[d], end = g_rowptr[d + 1];
        float2 self = __half22float2(g_h2h[d * 32 + lane]);
        float a00 = self.x, a10 = self.y;
        float a01 = 0.f, a11 = 0.f;
        int e = beg;
        for (; e + 32 <= end; e += 32) {
            int cv = g_col[e + lane];
            #pragma unroll
            for (int j = 0; j < 32; j += 2) {
                int s0 = __shfl_sync(0xffffffffu, cv, j);
                int s1 = __shfl_sync(0xffffffffu, cv, j + 1);
                float2 f0 = __half22float2(g_h2h[s0 * 32 + lane]);
                float2 f1 = __half22float2(g_h2h[s1 * 32 + lane]);
                a00 += f0.x; a10 += f0.y;
                a01 += f1.x; a11 += f1.y;
            }
        }
        if (e < end) {
            int n = end - e;
            int cv = (e + lane < end) ? g_col[e + lane] : 0;
            for (int j = 0; j < n; j++) {
                int s = __shfl_sync(0xffffffffu, cv, j);
                float2 f = __half22float2(g_h2h[s * 32 + lane]);
                a00 += f.x; a10 += f.y;
            }
        }
        float a0 = a00 + a01, a1 = a10 + a11;
        float di = g_dinv[d];
        float t0 = fmaxf(di * a0 + bias0, 0.f);
        float t1 = fmaxf(di * a1 + bias1, 0.f);
        // layer 1: u = relu(z2 @ Wo1 + bo1)
        zdup[wid][lane]      = make_float2(t0, t0);
        zdup[wid][lane + 32] = make_float2(t1, t1);
        __syncwarp();
        ull u2 = *(const ull*)&b1p[lane];
        #pragma unroll
        for (int j = 0; j < 64; j++)
            u2 = ffma2(*(const ull*)&zdup[wid][j], *(const ull*)&W1p[j * 32 + lane], u2);
        float2 u = unpack2(u2);
        u.x = fmaxf(u.x, 0.f); u.y = fmaxf(u.y, 0.f);
        __syncwarp();
        // layer 2: l = u @ Wo2 + bo2
        zdup[wid][lane]      = make_float2(u.x, u.x);
        zdup[wid][lane + 32] = make_float2(u.y, u.y);
        __syncwarp();
        ull l2 = *(const ull*)&b2p[lane];
        #pragma unroll
        for (int j = 0; j < 64; j++)
            l2 = ffma2(*(const ull*)&zdup[wid][j], *(const ull*)&W2p[j * 32 + lane], l2);
        __syncwarp();
        float2 l = unpack2(l2);
        float e0 = __expf(l.x), e1 = __expf(l.y);
        out[d * 64 + lane]      = e0;
        out[d * 64 + 32 + lane] = e1;
        ssum += e0 + e1;
    }
    #pragma unroll
    for (int o = 16; o > 0; o >>= 1) ssum += __shfl_xor_sync(0xffffffffu, ssum, o);
    if (lane == 0) wsum[wid] = ssum;
    __syncthreads();
    if (t == 0) {
        float s = 0.f;
        #pragma unroll
        for (int i = 0; i < 8; i++) s += wsum[i];
        g_part[blockIdx.x] = s;
    }
}

// ------------- finish softmax -------------------------------------------------
__global__ void reduce_sum_kernel(int n) {
    __shared__ float ws[8];
    int t = threadIdx.x, lane = t & 31, wid = t >> 5;
    float s = 0.f;
    for (int i = t; i < n; i += blockDim.x) s += g_part[i];
    #pragma unroll
    for (int o = 16; o > 0; o >>= 1) s += __shfl_xor_sync(0xffffffffu, s, o);
    if (lane == 0) ws[wid] = s;
    __syncthreads();
    if (t == 0) {
        float r = 0.f;
        for (int i = 0; i < (int)(blockDim.x >> 5); i++) r += ws[i];
        g_scalar[1] = 1.0f / r;
    }
}

__global__ void normalize_kernel(float* __restrict__ out, int total) {
    float inv = g_scalar[1];
    int i = (blockIdx.x * blockDim.x + threadIdx.x) * 4;
    if (i + 3 < total) {
        float4 v = *(float4*)(out + i);
        v.x *= inv; v.y *= inv; v.z *= inv; v.w *= inv;
        *(float4*)(out + i) = v;
    } else {
        for (int j = i; j < total; j++) out[j] *= inv;
    }
}

// ---------------- launch ----------------------------------------------------
extern "C" void kernel_launch(void* const* d_in, const int* in_sizes, int n_in,
                              void* d_out, int out_size) {
    const float* x  = (const float*)d_in[0];
    const int*   ei = (const int*)d_in[1];
    int base = n_in - 8;   // last 8: W1,b1,W2,b2,Wo1,bo1,Wo2,bo2
    const float* W1  = (const float*)d_in[base + 0];
    const float* b1  = (const float*)d_in[base + 1];
    const float* W2  = (const float*)d_in[base + 2];
    const float* b2  = (const float*)d_in[base + 3];
    const float* Wo1 = (const float*)d_in[base + 4];
    const float* bo1 = (const float*)d_in[base + 5];
    const float* Wo2 = (const float*)d_in[base + 6];
    const float* bo2 = (const float*)d_in[base + 7];
    float* out = (float*)d_out;

    int N = in_sizes[0] / IN_DIM;
    int E = in_sizes[1] / 2;
    int nb_scan = (N + 1023) / 1024;
    bool evenE = (E % 2) == 0;

    // side stream + fork/join events (created once, outside capture)
    static cudaStream_t s2 = nullptr;
    static cudaEvent_t evFork = nullptr, evJoin = nullptr;
    if (s2 == nullptr) {
        cudaStreamCreateWithFlags(&s2, cudaStreamNonBlocking);
        cudaEventCreateWithFlags(&evFork, cudaEventDisableTiming);
        cudaEventCreateWithFlags(&evJoin, cudaEventDisableTiming);
    }

    // fork: gemm1 runs on s2 concurrently with the CSR build on the main stream
    cudaEventRecord(evFork, 0);
    cudaStreamWaitEvent(s2, evFork, 0);
    int nWarpTiles = (N + 31) / 32;
    gemm1_kernel<<<(nWarpTiles + 7) / 8, 256, 0, s2>>>(x, W1, N);
    cudaEventRecord(evJoin, s2);

    // main stream: CSR build
    detect_zero_kernel<<<(N + 255) / 256, 256>>>((const unsigned int*)ei, 2 * E, N);
    if (evenE) hist_kernel<<<(E / 2 + 255) / 256, 256>>>(ei, E);
    else       hist_kernel_s<<<(E + 255) / 256, 256>>>(ei, E);
    scan1_kernel<<<nb_scan, 1024>>>(N);
    scan2_kernel<<<1, 32>>>(nb_scan);
    scan3a_kernel<<<(N + 255) / 256, 256>>>(N, E);
    if (evenE) fill_kernel<<<(E / 2 + 255) / 256, 256>>>(ei, E);
    else       fill_kernel_s<<<(E + 255) / 256, 256>>>(ei, E);

    // join: pack_h1 needs gemm1 (s2) + dinv (main)
    cudaStreamWaitEvent(0, evJoin, 0);
    pack_h1_kernel<<<(N + 255) / 256, 256>>>(N);

    // GCN layer 2 + head
    agg1_gemm2_kernel<<<2048, 256>>>(b1, W2, N);
    agg2_mlp_kernel<<<2048, 256>>>(b2, Wo1, bo1, Wo2, bo2, out, N);

    // softmax finish
    int total = out_size;
    reduce_sum_kernel<<<1, 256>>>(2048);
    normalize_kernel<<<(total / 4 + 255) / 256, 256>>>(out, total);
}

// round 10
// speedup vs baseline: 1.8565x; 1.3413x over previous
#include <cuda_runtime.h>
#include <cuda_fp16.h>

#define NN 100000
#define EE 3200000
#define IN_DIM 256
#define H1 32
#define H2 64

typedef unsigned long long ull;

// ---- packed f32x2 helpers (Blackwell FFMA2) --------------------------------
__device__ __forceinline__ ull ffma2(ull a, ull b, ull c) {
    ull d;
    asm("fma.rn.f32x2 %0, %1, %2, %3;" : "=l"(d) : "l"(a), "l"(b), "l"(c));
    return d;
}
__device__ __forceinline__ float2 unpack2(ull v) {
    float2 r;
    asm("mov.b64 {%0, %1}, %2;" : "=f"(r.x), "=f"(r.y) : "l"(v));
    return r;
}

// ---- tf32 mma helpers -------------------------------------------------------
__device__ __forceinline__ unsigned cvt_tf32(float f) {
    unsigned u;
    asm("cvt.rna.tf32.f32 %0, %1;" : "=r"(u) : "f"(f));
    return u;
}
__device__ __forceinline__ void mma_tf32(float c[4], unsigned a0, unsigned a1,
                                         unsigned a2, unsigned a3,
                                         unsigned b0, unsigned b1) {
    asm("mma.sync.aligned.m16n8k8.row.col.f32.tf32.tf32.f32 "
        "{%0,%1,%2,%3},{%4,%5,%6,%7},{%8,%9},{%0,%1,%2,%3};"
        : "+f"(c[0]), "+f"(c[1]), "+f"(c[2]), "+f"(c[3])
        : "r"(a0), "r"(a1), "r"(a2), "r"(a3), "r"(b0), "r"(b1));
}

// ---------------- static device scratch -------------------------------------
__device__ __align__(256) float   g_h1[NN * H1];   // x@W1 (fp32, unscaled)
__device__ __align__(256) __half2 g_h1h[NN * 16];  // scaled h1, pairs (c, c+16)
__device__ __align__(256) __half2 g_h2h[NN * 32];  // (z1@W2)*dinv, pairs (c, c+32)
__device__ __align__(256) __half  g_z2h[NN * 64];  // z2, row-major fp16
__device__ int   g_cnt[NN];
__device__ int   g_rowptr[NN + 1];
__device__ int   g_pos[NN];
__device__ int   g_col[EE];
__device__ float g_dinv[NN];
__device__ int   g_bsum[256];
__device__ float g_part[2048];
__device__ float g_scalar[2];
__device__ int   g_flag;        // 1 if edge index int64, 0 if int32

// ------------- zero counters + detect edge dtype ----------------------------
__global__ void detect_zero_kernel(const unsigned int* __restrict__ w, int n_vals, int N) {
    int i = blockIdx.x * blockDim.x + threadIdx.x;
    if (i < N) g_cnt[i] = 0;
    if (blockIdx.x == 0) {
        __shared__ unsigned int acc;
        if (threadIdx.x == 0) acc = 0u;
        __syncthreads();
        int K = n_vals < 2048 ? n_vals : 2048;
        unsigned int v = 0u;
        for (int j = threadIdx.x; j < K; j += blockDim.x) v |= w[2 * j + 1];
        atomicOr(&acc, v);
        __syncthreads();
        if (threadIdx.x == 0) g_flag = (acc == 0u) ? 1 : 0;
    }
}

// ------------- histogram of dst (2 edges/thread) ----------------------------
__global__ void hist_kernel(const int* __restrict__ buf, int E) {
    int e = (blockIdx.x * blockDim.x + threadIdx.x) * 2;
    if (e + 1 < E) {
        int d0, d1;
        if (g_flag) { int4 v = *(const int4*)&buf[2 * (E + e)]; d0 = v.x; d1 = v.z; }
        else        { int2 v = *(const int2*)&buf[E + e];       d0 = v.x; d1 = v.y; }
        atomicAdd(&g_cnt[d0], 1);
        atomicAdd(&g_cnt[d1], 1);
    } else if (e < E) {
        int d = g_flag ? buf[2 * (E + e)] : buf[E + e];
        atomicAdd(&g_cnt[d], 1);
    }
}

__global__ void hist_kernel_s(const int* __restrict__ buf, int E) {
    int e = blockIdx.x * blockDim.x + threadIdx.x;
    if (e < E) {
        int d = g_flag ? buf[2 * (E + e)] : buf[E + e];
        atomicAdd(&g_cnt[d], 1);
    }
}

// ------------- block scan ------------------------------------------------------
__global__ void scan1_kernel(int N) {
    __shared__ int sm[1024];
    int t = threadIdx.x;
    int i = blockIdx.x * 1024 + t;
    int x = (i < N) ? g_cnt[i] : 0;
    sm[t] = x;
    __syncthreads();
    for (int off = 1; off < 1024; off <<= 1) {
        int v = (t >= off) ? sm[t - off] : 0;
        __syncthreads();
        sm[t] += v;
        __syncthreads();
    }
    if (i < N) g_rowptr[i] = sm[t] - x;
    if (t == 1023) g_bsum[blockIdx.x] = sm[1023];
}

__global__ void scan2_kernel(int nb) {
    if (threadIdx.x == 0 && blockIdx.x == 0) {
        int run = 0;
        for (int b = 0; b < nb; b++) { int v = g_bsum[b]; g_bsum[b] = run; run += v; }
    }
}

// scan3a: finalize rowptr/pos/dinv only (independent of gemm1)
__global__ void scan3a_kernel(int N, int E) {
    int i = blockIdx.x * blockDim.x + threadIdx.x;
    if (i < N) {
        int r = g_rowptr[i] + g_bsum[i >> 10];
        g_rowptr[i] = r;
        g_pos[i]    = r;
        g_dinv[i]   = rsqrtf((float)(g_cnt[i] + 1));
        if (i == 0) g_rowptr[N] = E;
    }
}

// pack_h1: scale by dinv and pack to fp16 pairs (side stream, overlaps fill)
__global__ void pack_h1_kernel(int N) {
    int i = blockIdx.x * blockDim.x + threadIdx.x;
    if (i < N) {
        float di = g_dinv[i];
        float ch[32];
        const float4* h = (const float4*)&g_h1[i * H1];
        #pragma unroll
        for (int j = 0; j < 8; j++) {
            float4 v = h[j];
            ch[4 * j + 0] = v.x * di; ch[4 * j + 1] = v.y * di;
            ch[4 * j + 2] = v.z * di; ch[4 * j + 3] = v.w * di;
        }
        #pragma unroll
        for (int p = 0; p < 16; p++)
            g_h1h[i * 16 + p] = __floats2half2_rn(ch[p], ch[p + 16]);
    }
}

// ------------- GEMM1 via tf32 tensor cores (side stream) --------------------
__global__ void gemm1_kernel(const float* __restrict__ x,
                             const float* __restrict__ W1, int N) {
    __shared__ unsigned Bs[8192];   // [ks][nf][j][lane], 32 KB
    int t = threadIdx.x;
    for (int i = t; i < 8192; i += 256) {
        int lane2 = i & 31;
        int j  = (i >> 5) & 1;
        int nf = (i >> 6) & 3;
        int ks = i >> 8;
        int k = ks * 8 + (lane2 & 3) + j * 4;
        int n = nf * 8 + (lane2 >> 2);
        Bs[i] = cvt_tf32(W1[k * 32 + n]);
    }
    __syncthreads();
    int lane = t & 31, wid = t >> 5;
    int qrow = lane >> 2, qk = lane & 3;
    long r0 = (long)(blockIdx.x * 8 + wid) * 32;
    if (r0 >= N) return;
    long NL = N - 1;
    const float* p0 = x + (r0 + qrow      <= NL ? r0 + qrow      : NL) * 256 + qk;
    const float* p1 = x + (r0 + qrow + 8  <= NL ? r0 + qrow + 8  : NL) * 256 + qk;
    const float* p2 = x + (r0 + qrow + 16 <= NL ? r0 + qrow + 16 : NL) * 256 + qk;
    const float* p3 = x + (r0 + qrow + 24 <= NL ? r0 + qrow + 24 : NL) * 256 + qk;
    float c0[4][4] = {}, c1[4][4] = {};
    #pragma unroll 4
    for (int ks = 0; ks < 32; ks++) {
        int k0 = ks * 8;
        const unsigned* bp = &Bs[ks * 256 + lane];
        unsigned b00 = bp[0],   b01 = bp[32];
        unsigned b10 = bp[64],  b11 = bp[96];
        unsigned b20 = bp[128], b21 = bp[160];
        unsigned b30 = bp[192], b31 = bp[224];
        unsigned a0 = cvt_tf32(p0[k0]);
        unsigned a1 = cvt_tf32(p1[k0]);
        unsigned a2 = cvt_tf32(p0[k0 + 4]);
        unsigned a3 = cvt_tf32(p1[k0 + 4]);
        mma_tf32(c0[0], a0, a1, a2, a3, b00, b01);
        mma_tf32(c0[1], a0, a1, a2, a3, b10, b11);
        mma_tf32(c0[2], a0, a1, a2, a3, b20, b21);
        mma_tf32(c0[3], a0, a1, a2, a3, b30, b31);
        a0 = cvt_tf32(p2[k0]);
        a1 = cvt_tf32(p3[k0]);
        a2 = cvt_tf32(p2[k0 + 4]);
        a3 = cvt_tf32(p3[k0 + 4]);
        mma_tf32(c1[0], a0, a1, a2, a3, b00, b01);
        mma_tf32(c1[1], a0, a1, a2, a3, b10, b11);
        mma_tf32(c1[2], a0, a1, a2, a3, b20, b21);
        mma_tf32(c1[3], a0, a1, a2, a3, b30, b31);
    }
    long rw0 = r0 + qrow, rw1 = rw0 + 8, rw2 = rw0 + 16, rw3 = rw0 + 24;
    int cb = 2 * qk;
    #pragma unroll
    for (int nf = 0; nf < 4; nf++) {
        int col = nf * 8 + cb;
        if (rw0 < N) *(float2*)&g_h1[rw0 * 32 + col] = make_float2(c0[nf][0], c0[nf][1]);
        if (rw1 < N) *(float2*)&g_h1[rw1 * 32 + col] = make_float2(c0[nf][2], c0[nf][3]);
        if (rw2 < N) *(float2*)&g_h1[rw2 * 32 + col] = make_float2(c1[nf][0], c1[nf][1]);
        if (rw3 < N) *(float2*)&g_h1[rw3 * 32 + col] = make_float2(c1[nf][2], c1[nf][3]);
    }
}

// ------------- CSR fill (2 edges/thread) ------------------------------------
__global__ void fill_kernel(const int* __restrict__ buf, int E) {
    int e = (blockIdx.x * blockDim.x + threadIdx.x) * 2;
    if (e + 1 < E) {
        int s0, s1, d0, d1;
        if (g_flag) {
            int4 sv = *(const int4*)&buf[2 * e];        s0 = sv.x; s1 = sv.z;
            int4 dv = *(const int4*)&buf[2 * (E + e)];  d0 = dv.x; d1 = dv.z;
        } else {
            int2 sv = *(const int2*)&buf[e];        s0 = sv.x; s1 = sv.y;
            int2 dv = *(const int2*)&buf[E + e];    d0 = dv.x; d1 = dv.y;
        }
        int p0 = atomicAdd(&g_pos[d0], 1); g_col[p0] = s0;
        int p1 = atomicAdd(&g_pos[d1], 1); g_col[p1] = s1;
    } else if (e < E) {
        int s, d;
        if (g_flag) { d = buf[2 * (E + e)]; s = buf[2 * e]; }
        else        { d = buf[E + e];       s = buf[e]; }
        int p = atomicAdd(&g_pos[d], 1);
        g_col[p] = s;
    }
}

__global__ void fill_kernel_s(const int* __restrict__ buf, int E) {
    int e = blockIdx.x * blockDim.x + threadIdx.x;
    if (e < E) {
        int s, d;
        if (g_flag) { d = buf[2 * (E + e)]; s = buf[2 * e]; }
        else        { d = buf[E + e];       s = buf[e]; }
        int p = atomicAdd(&g_pos[d], 1);
        g_col[p] = s;
    }
}

// ------------- agg1 (fp16, 2 edges/warp-iter) + GEMV (FFMA2) ----------------
__global__ void agg1_gemm2_kernel(const float* __restrict__ b1,
                                  const float* __restrict__ W2, int N) {
    __shared__ float2 Wp[H1 * 32];   // Wp[k*32+c] = (W2[k][c], W2[k][c+32])
    __shared__ float2 zd[8][32];     // duplicated z pairs per warp
    int t = threadIdx.x;
    for (int i = t; i < H1 * 32; i += blockDim.x) {
        int k = i >> 5, c2 = i & 31;
        Wp[i] = make_float2(W2[k * H2 + c2], W2[k * H2 + 32 + c2]);
    }
    __syncthreads();
    int lane = t & 31, wid = t >> 5;
    int c = lane & 15;
    int hb = (lane >> 4) << 4;   // 0 or 16
    int gw = (blockIdx.x * blockDim.x + t) >> 5;
    int nw = (gridDim.x * blockDim.x) >> 5;
    float bias0 = b1[c], bias1 = b1[c + 16];
    for (int d = gw; d < N; d += nw) {
        int beg = g_rowptr[d], end = g_rowptr[d + 1];
        float aAx = 0.f, aAy = 0.f, aBx = 0.f, aBy = 0.f;
        int e = beg;
        for (; e + 32 <= end; e += 32) {
            int cv = g_col[e + lane];
            #pragma unroll
            for (int j = 0; j < 16; j += 2) {
                int s0 = __shfl_sync(0xffffffffu, cv, j + hb);
                int s1 = __shfl_sync(0xffffffffu, cv, j + 1 + hb);
                float2 f0 = __half22float2(g_h1h[s0 * 16 + c]);
                float2 f1 = __half22float2(g_h1h[s1 * 16 + c]);
                aAx += f0.x; aAy += f0.y;
                aBx += f1.x; aBy += f1.y;
            }
        }
        if (e < end) {
            int n = end - e;
            int cv = (e + lane < end) ? g_col[e + lane] : 0;
            int hodd = hb >> 4;                  // 0 or 1
            for (int j = 0; j < n; j += 2) {
                int idx = j + hodd;
                int s = __shfl_sync(0xffffffffu, cv, idx < n ? idx : 0);
                if (idx < n) {
                    float2 f = __half22float2(g_h1h[s * 16 + c]);
                    aAx += f.x; aAy += f.y;
                }
            }
        }
        float ax = aAx + aBx, ay = aAy + aBy;
        ax += __shfl_xor_sync(0xffffffffu, ax, 16);
        ay += __shfl_xor_sync(0xffffffffu, ay, 16);
        float2 sf = __half22float2(g_h1h[d * 16 + c]);   // self loop
        float di = g_dinv[d];
        float z0  = fmaxf(di * (ax + sf.x) + bias0, 0.f);
        float z16 = fmaxf(di * (ay + sf.y) + bias1, 0.f);
        zd[wid][c]      = make_float2(z0, z0);
        zd[wid][c + 16] = make_float2(z16, z16);
        __syncwarp();
        ull a2 = 0;
        #pragma unroll
        for (int k = 0; k < 32; k++)
            a2 = ffma2(*(const ull*)&zd[wid][k], *(const ull*)&Wp[k * 32 + lane], a2);
        __syncwarp();
        float2 a = unpack2(a2);
        g_h2h[d * 32 + lane] = __floats2half2_rn(a.x * di, a.y * di);
    }
}

// ------------- agg2: gather + bias + relu -> z2 (fp16 row-major) ------------
__global__ void agg2_kernel(const float* __restrict__ b2, int N) {
    __shared__ float bb[64];
    int t = threadIdx.x;
    if (t < 64) bb[t] = b2[t];
    __syncthreads();
    int lane = t & 31;
    int gw = (blockIdx.x * blockDim.x + t) >> 5;
    int nw = (gridDim.x * blockDim.x) >> 5;
    float bias0 = bb[lane], bias1 = bb[lane + 32];
    for (int d = gw; d < N; d += nw) {
        int beg = g_rowptr[d], end = g_rowptr[d + 1];
        float2 self = __half22float2(g_h2h[d * 32 + lane]);
        float a00 = self.x, a10 = self.y;
        float a01 = 0.f, a11 = 0.f;
        int e = beg;
        for (; e + 32 <= end; e += 32) {
            int cv = g_col[e + lane];
            #pragma unroll
            for (int j = 0; j < 32; j += 2) {
                int s0 = __shfl_sync(0xffffffffu, cv, j);
                int s1 = __shfl_sync(0xffffffffu, cv, j + 1);
                float2 f0 = __half22float2(g_h2h[s0 * 32 + lane]);
                float2 f1 = __half22float2(g_h2h[s1 * 32 + lane]);
                a00 += f0.x; a10 += f0.y;
                a01 += f1.x; a11 += f1.y;
            }
        }
        if (e < end) {
            int n = end - e;
            int cv = (e + lane < end) ? g_col[e + lane] : 0;
            for (int j = 0; j < n; j++) {
                int s = __shfl_sync(0xffffffffu, cv, j);
                float2 f = __half22float2(g_h2h[s * 32 + lane]);
                a00 += f.x; a10 += f.y;
            }
        }
        float di = g_dinv[d];
        float t0 = fmaxf(di * (a00 + a01) + bias0, 0.f);
        float t1 = fmaxf(di * (a10 + a11) + bias1, 0.f);
        g_z2h[d * 64 + lane]      = __float2half_rn(t0);
        g_z2h[d * 64 + 32 + lane] = __float2half_rn(t1);
    }
}

// ------------- MLP head via tf32 MMA: out = exp(relu(z2@Wo1+bo1)@Wo2+bo2) ---
#define UPITCH 68
#define MLP_SMEM (8192 * 4 + 8 * 32 * UPITCH * 4 + 128 * 4)
__global__ __launch_bounds__(256, 2)
void mlp_mma_kernel(const float* __restrict__ Wo1, const float* __restrict__ bo1,
                    const float* __restrict__ Wo2, const float* __restrict__ bo2,
                    float* __restrict__ out, int N) {
    extern __shared__ unsigned msm[];
    unsigned* Bs1 = msm;                         // 4096 u32
    unsigned* Bs2 = msm + 4096;                  // 4096 u32
    float* us  = (float*)(msm + 8192);           // 8 * 32 * 68 floats
    float* b1s = us + 8 * 32 * UPITCH;           // 64
    float* b2s = b1s + 64;                       // 64
    __shared__ float wsum[8];
    int t = threadIdx.x;
    for (int i = t; i < 4096; i += 256) {
        int lane2 = i & 31;
        int j  = (i >> 5) & 1;
        int nf = (i >> 6) & 7;
        int ks = (i >> 9) & 7;
        int k = ks * 8 + (lane2 & 3) + j * 4;
        int n = nf * 8 + (lane2 >> 2);
        Bs1[i] = cvt_tf32(Wo1[k * 64 + n]);
        Bs2[i] = cvt_tf32(Wo2[k * 64 + n]);
    }
    if (t < 64) { b1s[t] = bo1[t]; b2s[t] = bo2[t]; }
    __syncthreads();
    int lane = t & 31, wid = t >> 5;
    int qrow = lane >> 2, qk = lane & 3;
    long base = (long)(blockIdx.x * 8 + wid) * 32;
    float ssum = 0.f;
    if (base < N) {
        long NL = N - 1;
        long r0 = base + qrow      <= NL ? base + qrow      : NL;
        long r1 = base + qrow + 8  <= NL ? base + qrow + 8  : NL;
        long r2 = base + qrow + 16 <= NL ? base + qrow + 16 : NL;
        long r3 = base + qrow + 24 <= NL ? base + qrow + 24 : NL;
        float c0[8][4] = {}, c1[8][4] = {};
        #pragma unroll
        for (int ks = 0; ks < 8; ks++) {
            int k0 = ks * 8;
            unsigned a0 = cvt_tf32(__half2float(g_z2h[r0 * 64 + k0 + qk]));
            unsigned a1 = cvt_tf32(__half2float(g_z2h[r1 * 64 + k0 + qk]));
            unsigned a2 = cvt_tf32(__half2float(g_z2h[r0 * 64 + k0 + qk + 4]));
            unsigned a3 = cvt_tf32(__half2float(g_z2h[r1 * 64 + k0 + qk + 4]));
            unsigned a4 = cvt_tf32(__half2float(g_z2h[r2 * 64 + k0 + qk]));
            unsigned a5 = cvt_tf32(__half2float(g_z2h[r3 * 64 + k0 + qk]));
            unsigned a6 = cvt_tf32(__half2float(g_z2h[r2 * 64 + k0 + qk + 4]));
            unsigned a7 = cvt_tf32(__half2float(g_z2h[r3 * 64 + k0 + qk + 4]));
            const unsigned* bp = &Bs1[ks * 512 + lane];
            #pragma unroll
            for (int nf = 0; nf < 8; nf++) {
                unsigned b0 = bp[nf * 64], b1 = bp[nf * 64 + 32];
                mma_tf32(c0[nf], a0, a1, a2, a3, b0, b1);
                mma_tf32(c1[nf], a4, a5, a6, a7, b0, b1);
            }
        }
        // bias + relu -> smem u (pitch 68 floats: conflict-free frag reads)
        float* uw = us + wid * (32 * UPITCH);
        #pragma unroll
        for (int nf = 0; nf < 8; nf++) {
            int col = nf * 8 + 2 * qk;
            float bb0 = b1s[col], bb1 = b1s[col + 1];
            uw[qrow * UPITCH + col]            = fmaxf(c0[nf][0] + bb0, 0.f);
            uw[qrow * UPITCH + col + 1]        = fmaxf(c0[nf][1] + bb1, 0.f);
            uw[(qrow + 8) * UPITCH + col]      = fmaxf(c0[nf][2] + bb0, 0.f);
            uw[(qrow + 8) * UPITCH + col + 1]  = fmaxf(c0[nf][3] + bb1, 0.f);
            uw[(qrow + 16) * UPITCH + col]     = fmaxf(c1[nf][0] + bb0, 0.f);
            uw[(qrow + 16) * UPITCH + col + 1] = fmaxf(c1[nf][1] + bb1, 0.f);
            uw[(qrow + 24) * UPITCH + col]     = fmaxf(c1[nf][2] + bb0, 0.f);
            uw[(qrow + 24) * UPITCH + col + 1] = fmaxf(c1[nf][3] + bb1, 0.f);
        }
        __syncwarp();
        float d0[8][4] = {}, d1[8][4] = {};
        #pragma unroll
        for (int ks = 0; ks < 8; ks++) {
            int k0 = ks * 8;
            unsigned a0 = cvt_tf32(uw[qrow * UPITCH + k0 + qk]);
            unsigned a1 = cvt_tf32(uw[(qrow + 8) * UPITCH + k0 + qk]);
            unsigned a2 = cvt_tf32(uw[qrow * UPITCH + k0 + qk + 4]);
            unsigned a3 = cvt_tf32(uw[(qrow + 8) * UPITCH + k0 + qk + 4]);
            unsigned a4 = cvt_tf32(uw[(qrow + 16) * UPITCH + k0 + qk]);
            unsigned a5 = cvt_tf32(uw[(qrow + 24) * UPITCH + k0 + qk]);
            unsigned a6 = cvt_tf32(uw[(qrow + 16) * UPITCH + k0 + qk + 4]);
            unsigned a7 = cvt_tf32(uw[(qrow + 24) * UPITCH + k0 + qk + 4]);
            const unsigned* bp = &Bs2[ks * 512 + lane];
            #pragma unroll
            for (int nf = 0; nf < 8; nf++) {
                unsigned b0 = bp[nf * 64], b1 = bp[nf * 64 + 32];
                mma_tf32(d0[nf], a0, a1, a2, a3, b0, b1);
                mma_tf32(d1[nf], a4, a5, a6, a7, b0, b1);
            }
        }
        // bias + exp + store + sum
        #pragma unroll
        for (int nf = 0; nf < 8; nf++) {
            int col = nf * 8 + 2 * qk;
            float bb0 = b2s[col], bb1 = b2s[col + 1];
            long rw = base + qrow;
            float e0 = __expf(d0[nf][0] + bb0), e1 = __expf(d0[nf][1] + bb1);
            if (rw < N) { *(float2*)&out[rw * 64 + col] = make_float2(e0, e1); ssum += e0 + e1; }
            rw = base + qrow + 8;
            e0 = __expf(d0[nf][2] + bb0); e1 = __expf(d0[nf][3] + bb1);
            if (rw < N) { *(float2*)&out[rw * 64 + col] = make_float2(e0, e1); ssum += e0 + e1; }
            rw = base + qrow + 16;
            e0 = __expf(d1[nf][0] + bb0); e1 = __expf(d1[nf][1] + bb1);
            if (rw < N) { *(float2*)&out[rw * 64 + col] = make_float2(e0, e1); ssum += e0 + e1; }
            rw = base + qrow + 24;
            e0 = __expf(d1[nf][2] + bb0); e1 = __expf(d1[nf][3] + bb1);
            if (rw < N) { *(float2*)&out[rw * 64 + col] = make_float2(e0, e1); ssum += e0 + e1; }
        }
    }
    #pragma unroll
    for (int o = 16; o > 0; o >>= 1) ssum += __shfl_xor_sync(0xffffffffu, ssum, o);
    if (lane == 0) wsum[wid] = ssum;
    __syncthreads();
    if (t == 0) {
        float s = 0.f;
        #pragma unroll
        for (int i = 0; i < 8; i++) s += wsum[i];
        g_part[blockIdx.x] = s;
    }
}

// ------------- finish softmax -------------------------------------------------
__global__ void reduce_sum_kernel(int n) {
    __shared__ float ws[8];
    int t = threadIdx.x, lane = t & 31, wid = t >> 5;
    float s = 0.f;
    for (int i = t; i < n; i += blockDim.x) s += g_part[i];
    #pragma unroll
    for (int o = 16; o > 0; o >>= 1) s += __shfl_xor_sync(0xffffffffu, s, o);
    if (lane == 0) ws[wid] = s;
    __syncthreads();
    if (t == 0) {
        float r = 0.f;
        for (int i = 0; i < (int)(blockDim.x >> 5); i++) r += ws[i];
        g_scalar[1] = 1.0f / r;
    }
}

__global__ void normalize_kernel(float* __restrict__ out, int total) {
    float inv = g_scalar[1];
    int i = (blockIdx.x * blockDim.x + threadIdx.x) * 4;
    if (i + 3 < total) {
        float4 v = *(float4*)(out + i);
        v.x *= inv; v.y *= inv; v.z *= inv; v.w *= inv;
        *(float4*)(out + i) = v;
    } else {
        for (int j = i; j < total; j++) out[j] *= inv;
    }
}

// ---------------- launch ----------------------------------------------------
extern "C" void kernel_launch(void* const* d_in, const int* in_sizes, int n_in,
                              void* d_out, int out_size) {
    const float* x  = (const float*)d_in[0];
    const int*   ei = (const int*)d_in[1];
    int base = n_in - 8;   // last 8: W1,b1,W2,b2,Wo1,bo1,Wo2,bo2
    const float* W1  = (const float*)d_in[base + 0];
    const float* b1  = (const float*)d_in[base + 1];
    const float* W2  = (const float*)d_in[base + 2];
    const float* b2  = (const float*)d_in[base + 3];
    const float* Wo1 = (const float*)d_in[base + 4];
    const float* bo1 = (const float*)d_in[base + 5];
    const float* Wo2 = (const float*)d_in[base + 6];
    const float* bo2 = (const float*)d_in[base + 7];
    float* out = (float*)d_out;

    int N = in_sizes[0] / IN_DIM;
    int E = in_sizes[1] / 2;
    int nb_scan = (N + 1023) / 1024;
    bool evenE = (E % 2) == 0;

    static cudaStream_t s2 = nullptr;
    static cudaEvent_t evFork = nullptr, evDinv = nullptr, evJoin = nullptr;
    if (s2 == nullptr) {
        cudaStreamCreateWithFlags(&s2, cudaStreamNonBlocking);
        cudaEventCreateWithFlags(&evFork, cudaEventDisableTiming);
        cudaEventCreateWithFlags(&evDinv, cudaEventDisableTiming);
        cudaEventCreateWithFlags(&evJoin, cudaEventDisableTiming);
        cudaFuncSetAttribute(mlp_mma_kernel,
                             cudaFuncAttributeMaxDynamicSharedMemorySize, MLP_SMEM);
    }

    // fork: gemm1 on s2 overlaps the CSR build
    cudaEventRecord(evFork, 0);
    cudaStreamWaitEvent(s2, evFork, 0);
    int nWarpTiles = (N + 31) / 32;
    gemm1_kernel<<<(nWarpTiles + 7) / 8, 256, 0, s2>>>(x, W1, N);

    // main: CSR build up to dinv
    detect_zero_kernel<<<(N + 255) / 256, 256>>>((const unsigned int*)ei, 2 * E, N);
    if (evenE) hist_kernel<<<(E / 2 + 255) / 256, 256>>>(ei, E);
    else       hist_kernel_s<<<(E + 255) / 256, 256>>>(ei, E);
    scan1_kernel<<<nb_scan, 1024>>>(N);
    scan2_kernel<<<1, 32>>>(nb_scan);
    scan3a_kernel<<<(N + 255) / 256, 256>>>(N, E);
    cudaEventRecord(evDinv, 0);

    // s2: pack_h1 (needs gemm1 + dinv) overlaps fill on main
    cudaStreamWaitEvent(s2, evDinv, 0);
    pack_h1_kernel<<<(N + 255) / 256, 0 ? 0 : 256, 0, s2>>>(N);
    cudaEventRecord(evJoin, s2);

    // main: CSR fill
    if (evenE) fill_kernel<<<(E / 2 + 255) / 256, 256>>>(ei, E);
    else       fill_kernel_s<<<(E + 255) / 256, 256>>>(ei, E);

    // join
    cudaStreamWaitEvent(0, evJoin, 0);

    // GCN layer 2 + head
    agg1_gemm2_kernel<<<2048, 256>>>(b1, W2, N);
    agg2_kernel<<<2048, 256>>>(b2, N);
    int nblkMlp = (N + 255) / 256;
    mlp_mma_kernel<<<nblkMlp, 256, MLP_SMEM>>>(Wo1, bo1, Wo2, bo2, out, N);

    // softmax finish
    int total = out_size;
    reduce_sum_kernel<<<1, 256>>>(nblkMlp);
    normalize_kernel<<<(total / 4 + 255) / 256, 256>>>(out, total);
}